// round 9
// baseline (speedup 1.0000x reference)
#include <cuda_runtime.h>
#include <cuda_bf16.h>
#include <math.h>
#include <stdint.h>

// ---------------- problem constants ----------------
constexpr int BATCH = 64, HIMG = 56, WIMG = 56, CDIM = 192;
constexpr int HEADS = 6, HD = 32, WSZ = 7, SSZ = 3, NWG = 8, NTOK = 49;
constexpr int NWIN = BATCH * NWG * NWG;          // 4096
constexpr size_t ROWS = (size_t)NWIN * NTOK;     // 200704
constexpr int HID = 768, QKVC = 576;

// ---------------- scratch ----------------
__device__ __nv_bfloat16 g_xw [ROWS * CDIM];
__device__ __nv_bfloat16 g_qkv[ROWS * QKVC];
__device__ __nv_bfloat16 g_att[ROWS * CDIM];
__device__ __nv_bfloat16 g_hid[ROWS * HID];
__device__ __nv_bfloat16 g_wqkv[QKVC * CDIM];
__device__ __nv_bfloat16 g_wproj[CDIM * CDIM];
__device__ __nv_bfloat16 g_wfc1[HID * CDIM];
__device__ __nv_bfloat16 g_wfc2[CDIM * HID];
__device__ float g_tab[4 * HEADS * NTOK * 64];   // fused bias+mask, padded cols

// ---------------- helpers ----------------
__device__ __forceinline__ void ldsm4(uint32_t* r, uint32_t addr) {
    asm volatile("ldmatrix.sync.aligned.m8n8.x4.shared.b16 {%0,%1,%2,%3}, [%4];"
        : "=r"(r[0]), "=r"(r[1]), "=r"(r[2]), "=r"(r[3]) : "r"(addr));
}
__device__ __forceinline__ void mma_bf(float* c, const uint32_t* a, uint32_t b0, uint32_t b1) {
    asm volatile(
        "mma.sync.aligned.m16n8k16.row.col.f32.bf16.bf16.f32 "
        "{%0,%1,%2,%3}, {%4,%5,%6,%7}, {%8,%9}, {%0,%1,%2,%3};"
        : "+f"(c[0]), "+f"(c[1]), "+f"(c[2]), "+f"(c[3])
        : "r"(a[0]), "r"(a[1]), "r"(a[2]), "r"(a[3]), "r"(b0), "r"(b1));
}
__device__ __forceinline__ void cpa16(uint32_t dst, const void* src) {
    asm volatile("cp.async.cg.shared.global [%0], [%1], 16;" :: "r"(dst), "l"(src));
}
__device__ __forceinline__ void cpcommit() { asm volatile("cp.async.commit_group;"); }
template<int N> __device__ __forceinline__ void cpwait() {
    asm volatile("cp.async.wait_group %0;" :: "n"(N));
}
__device__ __forceinline__ float gelu_exact(float v) {
    return 0.5f * v * (1.0f + erff(v * 0.70710678118654752f));
}

// ---------------- fused weight conversion ----------------
__global__ void w2bf_all(const float* __restrict__ s0, const float* __restrict__ s1,
                         const float* __restrict__ s2, const float* __restrict__ s3,
                         __nv_bfloat16* __restrict__ d0, __nv_bfloat16* __restrict__ d1,
                         __nv_bfloat16* __restrict__ d2, __nv_bfloat16* __restrict__ d3)
{
    constexpr int N0 = QKVC * CDIM, N1 = CDIM * CDIM, N2 = HID * CDIM, N3 = CDIM * HID;
    int i = blockIdx.x * blockDim.x + threadIdx.x;
    if (i < N0) d0[i] = __float2bfloat16(s0[i]);
    int j = i - N0;
    if (j >= 0 && j < N1) d1[j] = __float2bfloat16(s1[j]);
    int k = j - N1;
    if (k >= 0 && k < N2) d2[k] = __float2bfloat16(s2[k]);
    int l = k - N2;
    if (l >= 0 && l < N3) d3[l] = __float2bfloat16(s3[l]);
}

// ---------------- fused bias+mask table: [cls][head][49][64] ----------------
__global__ void tab_kernel(const float* __restrict__ bias_table)
{
    const int cls = blockIdx.x / HEADS, h = blockIdx.x % HEADS;
    float* tp = g_tab + (size_t)blockIdx.x * NTOK * 64;
    for (int e = threadIdx.x; e < NTOK * 64; e += blockDim.x) {
        int n = e >> 6, m = e & 63;
        float v;
        if (m < NTOK) {
            int i1 = n / WSZ, j1 = n - i1 * WSZ;
            int i2 = m / WSZ, j2 = m - i2 * WSZ;
            int idx = (i1 - i2 + WSZ - 1) * (2 * WSZ - 1) + (j1 - j2 + WSZ - 1);
            int rh1 = (cls & 2) ? (i1 < 4 ? 1 : 2) : 0;
            int rw1 = (cls & 1) ? (j1 < 4 ? 1 : 2) : 0;
            int rh2 = (cls & 2) ? (i2 < 4 ? 1 : 2) : 0;
            int rw2 = (cls & 1) ? (j2 < 4 ? 1 : 2) : 0;
            float msk = (rh1 * 3 + rw1 == rh2 * 3 + rw2) ? 0.f : -100.f;
            v = bias_table[idx * HEADS + h] + msk;
        } else {
            v = -30000.f;
        }
        tp[e] = v;
    }
}

// ---------------- LayerNorm (+ optional shift/window gather), bf16 out ------
template<bool WIN>
__global__ void __launch_bounds__(256) ln_kernel(const float* __restrict__ x,
                                                 const float* __restrict__ gg,
                                                 const float* __restrict__ bb)
{
    int warp = (blockIdx.x << 3) + (threadIdx.x >> 5);
    int lane = threadIdx.x & 31;
    size_t src;
    if (WIN) {
        int w = warp / NTOK, n = warp - w * NTOK;
        int bi = w >> 6, wi = w & 63, wh = wi >> 3, ww = wi & 7;
        int ii = n / WSZ, jj = n - ii * WSZ;
        int hs = wh * WSZ + ii + SSZ; if (hs >= HIMG) hs -= HIMG;
        int ws_ = ww * WSZ + jj + SSZ; if (ws_ >= WIMG) ws_ -= WIMG;
        src = ((size_t)bi * (HIMG * WIMG) + (size_t)hs * WIMG + ws_) * CDIM;
    } else {
        src = (size_t)warp * CDIM;
    }
    const float* xr = x + src;
    float v[6]; float s = 0.f;
#pragma unroll
    for (int t = 0; t < 6; t++) { v[t] = xr[lane + 32 * t]; s += v[t]; }
#pragma unroll
    for (int o = 16; o; o >>= 1) s += __shfl_xor_sync(0xffffffffu, s, o);
    float mu = s * (1.0f / CDIM);
    float vs = 0.f;
#pragma unroll
    for (int t = 0; t < 6; t++) { float d = v[t] - mu; vs += d * d; }
#pragma unroll
    for (int o = 16; o; o >>= 1) vs += __shfl_xor_sync(0xffffffffu, vs, o);
    float inv = rsqrtf(vs * (1.0f / CDIM) + 1e-5f);
    __nv_bfloat16* op = g_xw + (size_t)warp * CDIM;
#pragma unroll
    for (int t = 0; t < 6; t++) {
        int c = lane + 32 * t;
        op[c] = __float2bfloat16((v[t] - mu) * inv * gg[c] + bb[c]);
    }
}

// ---------------- bf16 tensor-core GEMM --------------------------------------
// BM=128, BN=96, BK=32; 128 threads = 4 warps (2M x 2N), warp tile 64x48.
// 2-stage cp.async (.cg) double buffer.
enum { EPI_QKV = 0, EPI_PROJ = 1, EPI_FC1 = 2, EPI_FC2 = 3 };

template<int KD, int EPI>
__global__ void __launch_bounds__(128) gemm_bf(
    const __nv_bfloat16* __restrict__ A, const __nv_bfloat16* __restrict__ Wm,
    const float* __restrict__ bias, float* __restrict__ outf,
    __nv_bfloat16* __restrict__ outb, const float* __restrict__ extra)
{
    // As[2][128][20u32] (80B rows), Bs[2][96][20u32]
    __shared__ uint32_t sm[2 * 2560 + 2 * 1920];
    constexpr uint32_t ABUF = 10240u, BBUF = 7680u, BOFF = 2 * ABUF;
    const int t = threadIdx.x, lane = t & 31, w4 = t >> 5;
    const int warpM = w4 & 1, warpN = w4 >> 1;
    const int m0 = blockIdx.y * 128, n0 = blockIdx.x * 96;
    const int gid = lane >> 2, tig = lane & 3;
    const int lr = t >> 2, seg = t & 3;

    const __nv_bfloat16* Ap = A  + (size_t)(m0 + lr) * KD + seg * 8;
    const __nv_bfloat16* Bp = Wm + (size_t)(n0 + lr) * KD + seg * 8;
    const uint32_t smb = (uint32_t)__cvta_generic_to_shared(sm);
    const uint32_t aSt = smb + (uint32_t)((lr * 20 + seg * 4) * 4);
    const uint32_t bSt = smb + BOFF + (uint32_t)((lr * 20 + seg * 4) * 4);

    auto issue = [&](int buf, int k0) {
#pragma unroll
        for (int p = 0; p < 4; p++)
            cpa16(aSt + buf * ABUF + p * 2560u, Ap + (size_t)p * 32 * KD + k0);
#pragma unroll
        for (int q = 0; q < 3; q++)
            cpa16(bSt + buf * BBUF + q * 2560u, Bp + (size_t)q * 32 * KD + k0);
        cpcommit();
    };

    const uint32_t aRd = smb + (uint32_t)(((warpM * 64 + (lane & 15)) * 80) + (lane >> 4) * 16);
    const uint32_t bRd = smb + BOFF +
        (uint32_t)(((warpN * 48 + (lane & 7) + ((lane & 16) >> 1)) * 80) + ((lane >> 3) & 1) * 16);

    float acc[4][6][4];
#pragma unroll
    for (int i = 0; i < 4; i++)
#pragma unroll
        for (int j = 0; j < 6; j++)
#pragma unroll
            for (int r = 0; r < 4; r++) acc[i][j][r] = 0.f;

    constexpr int NIT = KD / 32;
    issue(0, 0);
    for (int it = 0; it < NIT; ++it) {
        const int cur = it & 1;
        cpwait<0>();
        __syncthreads();
        if (it + 1 < NIT) issue(cur ^ 1, (it + 1) * 32);
        const uint32_t aO = aRd + cur * ABUF;
        const uint32_t bO = bRd + cur * BBUF;
#pragma unroll
        for (int kk = 0; kk < 2; kk++) {
            uint32_t a[4][4], b[3][4];
#pragma unroll
            for (int mt = 0; mt < 4; mt++) ldsm4(a[mt], aO + mt * 1280u + kk * 32);
#pragma unroll
            for (int g = 0; g < 3; g++) ldsm4(b[g], bO + g * 1280u + kk * 32);
#pragma unroll
            for (int mt = 0; mt < 4; mt++)
#pragma unroll
                for (int g = 0; g < 3; g++) {
                    mma_bf(acc[mt][2 * g],     a[mt], b[g][0], b[g][1]);
                    mma_bf(acc[mt][2 * g + 1], a[mt], b[g][2], b[g][3]);
                }
        }
        __syncthreads();
    }

    const int mbase = m0 + warpM * 64;
    const int nbase = n0 + warpN * 48;
#pragma unroll
    for (int mt = 0; mt < 4; mt++) {
#pragma unroll
        for (int h = 0; h < 2; h++) {
            int r = mbase + mt * 16 + gid + h * 8;
            size_t dstrow = 0;
            if (EPI == EPI_PROJ) {
                int w = r / NTOK, n = r - w * NTOK;
                int bi = w >> 6, wi = w & 63, wh = wi >> 3, ww = wi & 7;
                int ii = n / WSZ, jj = n - ii * WSZ;
                int hp = wh * WSZ + ii + SSZ; if (hp >= HIMG) hp -= HIMG;
                int wp = ww * WSZ + jj + SSZ; if (wp >= WIMG) wp -= WIMG;
                dstrow = ((size_t)bi * (HIMG * WIMG) + (size_t)hp * WIMG + wp);
            }
#pragma unroll
            for (int nt = 0; nt < 6; nt++) {
                int n = nbase + nt * 8 + tig * 2;
                float2 bsv = *(const float2*)(bias + n);
                float vx = acc[mt][nt][2 * h]     + bsv.x;
                float vy = acc[mt][nt][2 * h + 1] + bsv.y;
                if (EPI == EPI_QKV) {
                    __nv_bfloat162 p(__float2bfloat16(vx), __float2bfloat16(vy));
                    *(__nv_bfloat162*)(outb + (size_t)r * QKVC + n) = p;
                } else if (EPI == EPI_PROJ) {
                    size_t dst = dstrow * CDIM + n;
                    float2 xv = *(const float2*)(extra + dst);
                    float2 v; v.x = vx + xv.x; v.y = vy + xv.y;
                    *(float2*)(outf + dst) = v;
                } else if (EPI == EPI_FC1) {
                    __nv_bfloat162 p(__float2bfloat16(gelu_exact(vx)),
                                     __float2bfloat16(gelu_exact(vy)));
                    *(__nv_bfloat162*)(outb + (size_t)r * HID + n) = p;
                } else {
                    float2 xv = *(const float2*)(outf + (size_t)r * CDIM + n);
                    float2 v; v.x = vx + xv.x; v.y = vy + xv.y;
                    *(float2*)(outf + (size_t)r * CDIM + n) = v;
                }
            }
        }
    }
}

// ---------------- tensor-core window attention (fused-table softmax) ---------
__global__ void __launch_bounds__(128) attn_tc()
{
    __shared__ uint32_t sm[1280 + 1280 + 1152 + 2304];
    constexpr int QS = 0, KS = 1280, VT = 2560, PS = 3712;

    const int blk = blockIdx.x;
    const int w = blk / HEADS, h = blk - w * HEADS;
    const int t = threadIdx.x, lane = t & 31, w4 = t >> 5;
    const int gid = lane >> 2, tig = lane & 3;

    char* smc = (char*)sm;
    const __nv_bfloat16* base = g_qkv + (size_t)w * NTOK * QKVC + (size_t)h * HD;

    for (int e = t; e < NTOK * 4; e += 128) {
        int n = e >> 2, s = e & 3;
        const char* rp = (const char*)(base + (size_t)n * QKVC) + s * 16;
        *(uint4*)(smc + QS * 4 + n * 80 + s * 16) = *(const uint4*)rp;
        *(uint4*)(smc + KS * 4 + n * 80 + s * 16) = *(const uint4*)(rp + CDIM * 2);
    }
    for (int e = t; e < 15 * 4; e += 128) {
        int n = 49 + (e >> 2), s = e & 3;
        uint4 z = {0, 0, 0, 0};
        *(uint4*)(smc + QS * 4 + n * 80 + s * 16) = z;
        *(uint4*)(smc + KS * 4 + n * 80 + s * 16) = z;
    }
    for (int e = t; e < NTOK * HD; e += 128) {
        int n = e >> 5, d = e & 31;
        ((__nv_bfloat16*)(smc + VT * 4 + d * 144))[n] = base[(size_t)n * QKVC + 2 * CDIM + d];
    }
    for (int e = t; e < HD * 15; e += 128) {
        int d = e / 15, n = 49 + e % 15;
        ((__nv_bfloat16*)(smc + VT * 4 + d * 144))[n] = __nv_bfloat16(0.f);
    }
    __syncthreads();

    const uint32_t smb = (uint32_t)__cvta_generic_to_shared(sm);
    const uint32_t aQ = smb + QS * 4 + (w4 * 16 + (lane & 15)) * 80 + (lane >> 4) * 16;
    const uint32_t bK = smb + KS * 4 +
        ((lane & 7) + ((lane & 16) >> 1)) * 80 + ((lane >> 3) & 1) * 16;
    float acc[8][4];
#pragma unroll
    for (int i = 0; i < 8; i++)
#pragma unroll
        for (int j = 0; j < 4; j++) acc[i][j] = 0.f;
#pragma unroll
    for (int kk = 0; kk < 2; kk++) {
        uint32_t a[4]; ldsm4(a, aQ + kk * 32);
#pragma unroll
        for (int ntp = 0; ntp < 4; ntp++) {
            uint32_t b[4]; ldsm4(b, bK + ntp * 1280u + kk * 32);
            mma_bf(acc[2 * ntp],     a, b[0], b[1]);
            mma_bf(acc[2 * ntp + 1], a, b[2], b[3]);
        }
    }

    const int wi = w & 63;
    const int cls = (((wi >> 3) == 7) ? 2 : 0) | (((wi & 7) == 7) ? 1 : 0);
    const float* tabh = g_tab + (size_t)(cls * HEADS + h) * NTOK * 64;

    const float scale = 0.17677669529663688f;
#pragma unroll
    for (int rr = 0; rr < 2; rr++) {
        int r = w4 * 16 + gid + rr * 8;
        const bool rv = (r < NTOK);
        const float* trow = tabh + (size_t)(rv ? r : 0) * 64 + tig * 2;
        float vv[16]; float mx = -1e30f;
#pragma unroll
        for (int nt = 0; nt < 8; nt++) {
            float2 tv = *(const float2*)(trow + nt * 8);
            float v0 = rv ? acc[nt][2 * rr]     * scale + tv.x : -1e30f;
            float v1 = rv ? acc[nt][2 * rr + 1] * scale + tv.y : -1e30f;
            vv[2 * nt] = v0; vv[2 * nt + 1] = v1;
            mx = fmaxf(mx, fmaxf(v0, v1));
        }
        mx = fmaxf(mx, __shfl_xor_sync(0xffffffffu, mx, 1));
        mx = fmaxf(mx, __shfl_xor_sync(0xffffffffu, mx, 2));
        float sum = 0.f;
#pragma unroll
        for (int i = 0; i < 16; i++) { vv[i] = __expf(vv[i] - mx); sum += vv[i]; }
        sum += __shfl_xor_sync(0xffffffffu, sum, 1);
        sum += __shfl_xor_sync(0xffffffffu, sum, 2);
        float inv = 1.0f / sum;
#pragma unroll
        for (int nt = 0; nt < 8; nt++) {
            int c = nt * 8 + tig * 2;
            __nv_bfloat162 p(__float2bfloat16(vv[2 * nt] * inv),
                             __float2bfloat16(vv[2 * nt + 1] * inv));
            *(__nv_bfloat162*)(smc + PS * 4 + r * 144 + c * 2) = p;
        }
    }
    __syncwarp();

    const uint32_t aP = smb + PS * 4 + (w4 * 16 + (lane & 15)) * 144 + (lane >> 4) * 16;
    const uint32_t bV = smb + VT * 4 +
        ((lane & 7) + ((lane & 16) >> 1)) * 144 + ((lane >> 3) & 1) * 16;
    float oa[4][4];
#pragma unroll
    for (int i = 0; i < 4; i++)
#pragma unroll
        for (int j = 0; j < 4; j++) oa[i][j] = 0.f;
#pragma unroll
    for (int ks = 0; ks < 4; ks++) {
        uint32_t a[4]; ldsm4(a, aP + ks * 32);
        uint32_t b0[4], b1[4];
        ldsm4(b0, bV + ks * 32);
        ldsm4(b1, bV + 16 * 144 + ks * 32);
        mma_bf(oa[0], a, b0[0], b0[1]);
        mma_bf(oa[1], a, b0[2], b0[3]);
        mma_bf(oa[2], a, b1[0], b1[1]);
        mma_bf(oa[3], a, b1[2], b1[3]);
    }
    __nv_bfloat16* ob = g_att + (size_t)w * NTOK * CDIM + (size_t)h * HD;
#pragma unroll
    for (int rr = 0; rr < 2; rr++) {
        int r = w4 * 16 + gid + rr * 8;
        if (r < NTOK) {
#pragma unroll
            for (int nt = 0; nt < 4; nt++) {
                int c = nt * 8 + tig * 2;
                __nv_bfloat162 p(__float2bfloat16(oa[nt][2 * rr]),
                                 __float2bfloat16(oa[nt][2 * rr + 1]));
                *(__nv_bfloat162*)(ob + (size_t)r * CDIM + c) = p;
            }
        }
    }
}

// ---------------- launch ----------------------------------------------------
extern "C" void kernel_launch(void* const* d_in, const int* in_sizes, int n_in,
                              void* d_out, int out_size)
{
    const float* x      = (const float*)d_in[0];
    const float* n1g    = (const float*)d_in[1];
    const float* n1b    = (const float*)d_in[2];
    const float* qkv_w  = (const float*)d_in[3];
    const float* qkv_b  = (const float*)d_in[4];
    const float* relb   = (const float*)d_in[5];
    const float* proj_w = (const float*)d_in[6];
    const float* proj_b = (const float*)d_in[7];
    const float* n2g    = (const float*)d_in[8];
    const float* n2b    = (const float*)d_in[9];
    const float* fc1_w  = (const float*)d_in[10];
    const float* fc1_b  = (const float*)d_in[11];
    const float* fc2_w  = (const float*)d_in[12];
    const float* fc2_b  = (const float*)d_in[13];
    float* out = (float*)d_out;

    __nv_bfloat16 *pxw, *pqkv, *patt, *phid, *pwqkv, *pwproj, *pwfc1, *pwfc2;
    cudaGetSymbolAddress((void**)&pxw,   g_xw);
    cudaGetSymbolAddress((void**)&pqkv,  g_qkv);
    cudaGetSymbolAddress((void**)&patt,  g_att);
    cudaGetSymbolAddress((void**)&phid,  g_hid);
    cudaGetSymbolAddress((void**)&pwqkv, g_wqkv);
    cudaGetSymbolAddress((void**)&pwproj,g_wproj);
    cudaGetSymbolAddress((void**)&pwfc1, g_wfc1);
    cudaGetSymbolAddress((void**)&pwfc2, g_wfc2);

    const int LN_BLOCKS = (int)(ROWS / 8);       // 25088
    const int MB = (int)(ROWS / 128);            // 1568
    constexpr int WTOT = QKVC * CDIM + CDIM * CDIM + HID * CDIM + CDIM * HID;

    w2bf_all<<<(WTOT + 255) / 256, 256>>>(qkv_w, proj_w, fc1_w, fc2_w,
                                          pwqkv, pwproj, pwfc1, pwfc2);
    tab_kernel<<<4 * HEADS, 256>>>(relb);

    ln_kernel<true><<<LN_BLOCKS, 256>>>(x, n1g, n1b);
    gemm_bf<192, EPI_QKV><<<dim3(QKVC / 96, MB), 128>>>(pxw, pwqkv, qkv_b, nullptr, pqkv, nullptr);
    attn_tc<<<NWIN * HEADS, 128>>>();
    gemm_bf<192, EPI_PROJ><<<dim3(CDIM / 96, MB), 128>>>(patt, pwproj, proj_b, out, nullptr, x);
    ln_kernel<false><<<LN_BLOCKS, 256>>>(out, n2g, n2b);
    gemm_bf<192, EPI_FC1><<<dim3(HID / 96, MB), 128>>>(pxw, pwfc1, fc1_b, nullptr, phid, nullptr);
    gemm_bf<768, EPI_FC2><<<dim3(CDIM / 96, MB), 128>>>(phid, pwfc2, fc2_b, out, nullptr, nullptr);
}

// round 10
// speedup vs baseline: 1.1166x; 1.1166x over previous
#include <cuda_runtime.h>
#include <cuda_bf16.h>
#include <math.h>
#include <stdint.h>

// ---------------- problem constants ----------------
constexpr int BATCH = 64, HIMG = 56, WIMG = 56, CDIM = 192;
constexpr int HEADS = 6, HD = 32, WSZ = 7, SSZ = 3, NWG = 8, NTOK = 49;
constexpr int NWIN = BATCH * NWG * NWG;          // 4096
constexpr size_t ROWS = (size_t)NWIN * NTOK;     // 200704
constexpr int HID = 768, QKVC = 576;

// ---------------- scratch ----------------
__device__ __nv_bfloat16 g_xw [ROWS * CDIM];
__device__ __nv_bfloat16 g_qkv[ROWS * QKVC];
__device__ __nv_bfloat16 g_att[ROWS * CDIM];
__device__ __nv_bfloat16 g_hid[ROWS * HID];
__device__ __nv_bfloat16 g_wqkv[QKVC * CDIM];
__device__ __nv_bfloat16 g_wproj[CDIM * CDIM];
__device__ __nv_bfloat16 g_wfc1[HID * CDIM];
__device__ __nv_bfloat16 g_wfc2[CDIM * HID];
__device__ float g_tab[4 * HEADS * NTOK * 64];   // fused bias+mask, padded cols

// ---------------- helpers ----------------
__device__ __forceinline__ void ldsm4(uint32_t* r, uint32_t addr) {
    asm volatile("ldmatrix.sync.aligned.m8n8.x4.shared.b16 {%0,%1,%2,%3}, [%4];"
        : "=r"(r[0]), "=r"(r[1]), "=r"(r[2]), "=r"(r[3]) : "r"(addr));
}
__device__ __forceinline__ void mma_bf(float* c, const uint32_t* a, uint32_t b0, uint32_t b1) {
    asm volatile(
        "mma.sync.aligned.m16n8k16.row.col.f32.bf16.bf16.f32 "
        "{%0,%1,%2,%3}, {%4,%5,%6,%7}, {%8,%9}, {%0,%1,%2,%3};"
        : "+f"(c[0]), "+f"(c[1]), "+f"(c[2]), "+f"(c[3])
        : "r"(a[0]), "r"(a[1]), "r"(a[2]), "r"(a[3]), "r"(b0), "r"(b1));
}
__device__ __forceinline__ void cpa16ca(uint32_t dst, const void* src) {
    asm volatile("cp.async.ca.shared.global [%0], [%1], 16;" :: "r"(dst), "l"(src));
}
__device__ __forceinline__ void cpa16cg(uint32_t dst, const void* src) {
    asm volatile("cp.async.cg.shared.global [%0], [%1], 16;" :: "r"(dst), "l"(src));
}
__device__ __forceinline__ void cpcommit() { asm volatile("cp.async.commit_group;"); }
template<int N> __device__ __forceinline__ void cpwait() {
    asm volatile("cp.async.wait_group %0;" :: "n"(N));
}
__device__ __forceinline__ float gelu_exact(float v) {
    return 0.5f * v * (1.0f + erff(v * 0.70710678118654752f));
}

// ---------------- fused weight conversion ----------------
__global__ void w2bf_all(const float* __restrict__ s0, const float* __restrict__ s1,
                         const float* __restrict__ s2, const float* __restrict__ s3,
                         __nv_bfloat16* __restrict__ d0, __nv_bfloat16* __restrict__ d1,
                         __nv_bfloat16* __restrict__ d2, __nv_bfloat16* __restrict__ d3)
{
    constexpr int N0 = QKVC * CDIM, N1 = CDIM * CDIM, N2 = HID * CDIM, N3 = CDIM * HID;
    int i = blockIdx.x * blockDim.x + threadIdx.x;
    if (i < N0) d0[i] = __float2bfloat16(s0[i]);
    int j = i - N0;
    if (j >= 0 && j < N1) d1[j] = __float2bfloat16(s1[j]);
    int k = j - N1;
    if (k >= 0 && k < N2) d2[k] = __float2bfloat16(s2[k]);
    int l = k - N2;
    if (l >= 0 && l < N3) d3[l] = __float2bfloat16(s3[l]);
}

// ---------------- fused bias+mask table: [cls][head][49][64] ----------------
__global__ void tab_kernel(const float* __restrict__ bias_table)
{
    const int cls = blockIdx.x / HEADS, h = blockIdx.x % HEADS;
    float* tp = g_tab + (size_t)blockIdx.x * NTOK * 64;
    for (int e = threadIdx.x; e < NTOK * 64; e += blockDim.x) {
        int n = e >> 6, m = e & 63;
        float v;
        if (m < NTOK) {
            int i1 = n / WSZ, j1 = n - i1 * WSZ;
            int i2 = m / WSZ, j2 = m - i2 * WSZ;
            int idx = (i1 - i2 + WSZ - 1) * (2 * WSZ - 1) + (j1 - j2 + WSZ - 1);
            int rh1 = (cls & 2) ? (i1 < 4 ? 1 : 2) : 0;
            int rw1 = (cls & 1) ? (j1 < 4 ? 1 : 2) : 0;
            int rh2 = (cls & 2) ? (i2 < 4 ? 1 : 2) : 0;
            int rw2 = (cls & 1) ? (j2 < 4 ? 1 : 2) : 0;
            float msk = (rh1 * 3 + rw1 == rh2 * 3 + rw2) ? 0.f : -100.f;
            v = bias_table[idx * HEADS + h] + msk;
        } else {
            v = -30000.f;
        }
        tp[e] = v;
    }
}

// ---------------- LayerNorm (+ optional shift/window gather), bf16 out ------
template<bool WIN>
__global__ void __launch_bounds__(256) ln_kernel(const float* __restrict__ x,
                                                 const float* __restrict__ gg,
                                                 const float* __restrict__ bb)
{
    int warp = (blockIdx.x << 3) + (threadIdx.x >> 5);
    int lane = threadIdx.x & 31;
    size_t src;
    if (WIN) {
        int w = warp / NTOK, n = warp - w * NTOK;
        int bi = w >> 6, wi = w & 63, wh = wi >> 3, ww = wi & 7;
        int ii = n / WSZ, jj = n - ii * WSZ;
        int hs = wh * WSZ + ii + SSZ; if (hs >= HIMG) hs -= HIMG;
        int ws_ = ww * WSZ + jj + SSZ; if (ws_ >= WIMG) ws_ -= WIMG;
        src = ((size_t)bi * (HIMG * WIMG) + (size_t)hs * WIMG + ws_) * CDIM;
    } else {
        src = (size_t)warp * CDIM;
    }
    const float* xr = x + src;
    float v[6]; float s = 0.f;
#pragma unroll
    for (int t = 0; t < 6; t++) { v[t] = xr[lane + 32 * t]; s += v[t]; }
#pragma unroll
    for (int o = 16; o; o >>= 1) s += __shfl_xor_sync(0xffffffffu, s, o);
    float mu = s * (1.0f / CDIM);
    float vs = 0.f;
#pragma unroll
    for (int t = 0; t < 6; t++) { float d = v[t] - mu; vs += d * d; }
#pragma unroll
    for (int o = 16; o; o >>= 1) vs += __shfl_xor_sync(0xffffffffu, vs, o);
    float inv = rsqrtf(vs * (1.0f / CDIM) + 1e-5f);
    __nv_bfloat16* op = g_xw + (size_t)warp * CDIM;
#pragma unroll
    for (int t = 0; t < 6; t++) {
        int c = lane + 32 * t;
        op[c] = __float2bfloat16((v[t] - mu) * inv * gg[c] + bb[c]);
    }
}

enum { EPI_QKV = 0, EPI_PROJ = 1, EPI_FC1 = 2, EPI_FC2 = 3 };

// ---------------- GEMM A: BM=128, BN=96 (QKV only; measured 183us) ----------
template<int KD, int EPI>
__global__ void __launch_bounds__(128) gemm_bf96(
    const __nv_bfloat16* __restrict__ A, const __nv_bfloat16* __restrict__ Wm,
    const float* __restrict__ bias, float* __restrict__ outf,
    __nv_bfloat16* __restrict__ outb, const float* __restrict__ extra)
{
    __shared__ uint32_t sm[2 * 2560 + 2 * 1920];
    constexpr uint32_t ABUF = 10240u, BBUF = 7680u, BOFF = 2 * ABUF;
    const int t = threadIdx.x, lane = t & 31, w4 = t >> 5;
    const int warpM = w4 & 1, warpN = w4 >> 1;
    const int m0 = blockIdx.y * 128, n0 = blockIdx.x * 96;
    const int gid = lane >> 2, tig = lane & 3;
    const int lr = t >> 2, seg = t & 3;

    const __nv_bfloat16* Ap = A  + (size_t)(m0 + lr) * KD + seg * 8;
    const __nv_bfloat16* Bp = Wm + (size_t)(n0 + lr) * KD + seg * 8;
    const uint32_t smb = (uint32_t)__cvta_generic_to_shared(sm);
    const uint32_t aSt = smb + (uint32_t)((lr * 20 + seg * 4) * 4);
    const uint32_t bSt = smb + BOFF + (uint32_t)((lr * 20 + seg * 4) * 4);

    auto issue = [&](int buf, int k0) {
#pragma unroll
        for (int p = 0; p < 4; p++)
            cpa16cg(aSt + buf * ABUF + p * 2560u, Ap + (size_t)p * 32 * KD + k0);
#pragma unroll
        for (int q = 0; q < 3; q++)
            cpa16cg(bSt + buf * BBUF + q * 2560u, Bp + (size_t)q * 32 * KD + k0);
        cpcommit();
    };

    const uint32_t aRd = smb + (uint32_t)(((warpM * 64 + (lane & 15)) * 80) + (lane >> 4) * 16);
    const uint32_t bRd = smb + BOFF +
        (uint32_t)(((warpN * 48 + (lane & 7) + ((lane & 16) >> 1)) * 80) + ((lane >> 3) & 1) * 16);

    float acc[4][6][4];
#pragma unroll
    for (int i = 0; i < 4; i++)
#pragma unroll
        for (int j = 0; j < 6; j++)
#pragma unroll
            for (int r = 0; r < 4; r++) acc[i][j][r] = 0.f;

    constexpr int NIT = KD / 32;
    issue(0, 0);
    for (int it = 0; it < NIT; ++it) {
        const int cur = it & 1;
        cpwait<0>();
        __syncthreads();
        if (it + 1 < NIT) issue(cur ^ 1, (it + 1) * 32);
        const uint32_t aO = aRd + cur * ABUF;
        const uint32_t bO = bRd + cur * BBUF;
#pragma unroll
        for (int kk = 0; kk < 2; kk++) {
            uint32_t a[4][4], b[3][4];
#pragma unroll
            for (int mt = 0; mt < 4; mt++) ldsm4(a[mt], aO + mt * 1280u + kk * 32);
#pragma unroll
            for (int g = 0; g < 3; g++) ldsm4(b[g], bO + g * 1280u + kk * 32);
#pragma unroll
            for (int mt = 0; mt < 4; mt++)
#pragma unroll
                for (int g = 0; g < 3; g++) {
                    mma_bf(acc[mt][2 * g],     a[mt], b[g][0], b[g][1]);
                    mma_bf(acc[mt][2 * g + 1], a[mt], b[g][2], b[g][3]);
                }
        }
        __syncthreads();
    }

    const int mbase = m0 + warpM * 64;
    const int nbase = n0 + warpN * 48;
#pragma unroll
    for (int mt = 0; mt < 4; mt++) {
#pragma unroll
        for (int h = 0; h < 2; h++) {
            int r = mbase + mt * 16 + gid + h * 8;
#pragma unroll
            for (int nt = 0; nt < 6; nt++) {
                int n = nbase + nt * 8 + tig * 2;
                float2 bsv = *(const float2*)(bias + n);
                float vx = acc[mt][nt][2 * h]     + bsv.x;
                float vy = acc[mt][nt][2 * h + 1] + bsv.y;
                __nv_bfloat162 p(__float2bfloat16(vx), __float2bfloat16(vy));
                *(__nv_bfloat162*)(outb + (size_t)r * QKVC + n) = p;
            }
        }
    }
}

// ---------------- GEMM B: BM=128, BN=64 (R7 config; proj/fc1/fc2) -----------
template<int KD, int EPI>
__global__ void __launch_bounds__(128) gemm_bf64(
    const __nv_bfloat16* __restrict__ A, const __nv_bfloat16* __restrict__ Wm,
    const float* __restrict__ bias, float* __restrict__ outf,
    __nv_bfloat16* __restrict__ outb, const float* __restrict__ extra)
{
    __shared__ uint32_t sm[2 * 2560 + 2 * 1280];
    const int t = threadIdx.x, lane = t & 31, w4 = t >> 5;
    const int warpM = w4 & 1, warpN = w4 >> 1;
    const int m0 = blockIdx.y * 128, n0 = blockIdx.x * 64;
    const int gid = lane >> 2, tig = lane & 3;
    const int lr = t >> 2, seg = t & 3;

    const __nv_bfloat16* Ap = A  + (size_t)(m0 + lr) * KD + seg * 8;
    const __nv_bfloat16* Bp = Wm + (size_t)(n0 + lr) * KD + seg * 8;
    const uint32_t smb = (uint32_t)__cvta_generic_to_shared(sm);
    const uint32_t aSt = smb + (uint32_t)((lr * 20 + seg * 4) * 4);
    const uint32_t bSt = smb + 20480u + (uint32_t)((lr * 20 + seg * 4) * 4);

    auto issue = [&](int buf, int k0) {
#pragma unroll
        for (int p = 0; p < 4; p++)
            cpa16ca(aSt + buf * 10240u + p * 2560u, Ap + (size_t)p * 32 * KD + k0);
#pragma unroll
        for (int q = 0; q < 2; q++)
            cpa16ca(bSt + buf * 5120u + q * 2560u, Bp + (size_t)q * 32 * KD + k0);
        cpcommit();
    };

    const uint32_t aRd = smb + (uint32_t)(((warpM * 64 + (lane & 15)) * 80) + (lane >> 4) * 16);
    const uint32_t bRd = smb + 20480u +
        (uint32_t)(((warpN * 32 + (lane & 7) + ((lane & 16) >> 1)) * 80) + ((lane >> 3) & 1) * 16);

    float acc[4][4][4];
#pragma unroll
    for (int i = 0; i < 4; i++)
#pragma unroll
        for (int j = 0; j < 4; j++)
#pragma unroll
            for (int r = 0; r < 4; r++) acc[i][j][r] = 0.f;

    constexpr int NIT = KD / 32;
    issue(0, 0);
    for (int it = 0; it < NIT; ++it) {
        const int cur = it & 1;
        cpwait<0>();
        __syncthreads();
        if (it + 1 < NIT) issue(cur ^ 1, (it + 1) * 32);
        const uint32_t aO = aRd + cur * 10240u;
        const uint32_t bO = bRd + cur * 5120u;
#pragma unroll
        for (int kk = 0; kk < 2; kk++) {
            uint32_t a[4][4], b0[4], b1[4];
#pragma unroll
            for (int mt = 0; mt < 4; mt++) ldsm4(a[mt], aO + mt * 1280u + kk * 32);
            ldsm4(b0, bO + kk * 32);
            ldsm4(b1, bO + 1280u + kk * 32);
#pragma unroll
            for (int mt = 0; mt < 4; mt++) {
                mma_bf(acc[mt][0], a[mt], b0[0], b0[1]);
                mma_bf(acc[mt][1], a[mt], b0[2], b0[3]);
                mma_bf(acc[mt][2], a[mt], b1[0], b1[1]);
                mma_bf(acc[mt][3], a[mt], b1[2], b1[3]);
            }
        }
        __syncthreads();
    }

    const int mbase = m0 + warpM * 64;
    const int nbase = n0 + warpN * 32;
#pragma unroll
    for (int mt = 0; mt < 4; mt++) {
#pragma unroll
        for (int h = 0; h < 2; h++) {
            int r = mbase + mt * 16 + gid + h * 8;
            size_t dstrow = 0;
            if (EPI == EPI_PROJ) {
                int w = r / NTOK, n = r - w * NTOK;
                int bi = w >> 6, wi = w & 63, wh = wi >> 3, ww = wi & 7;
                int ii = n / WSZ, jj = n - ii * WSZ;
                int hp = wh * WSZ + ii + SSZ; if (hp >= HIMG) hp -= HIMG;
                int wp = ww * WSZ + jj + SSZ; if (wp >= WIMG) wp -= WIMG;
                dstrow = ((size_t)bi * (HIMG * WIMG) + (size_t)hp * WIMG + wp);
            }
#pragma unroll
            for (int nt = 0; nt < 4; nt++) {
                int n = nbase + nt * 8 + tig * 2;
                float2 bsv = *(const float2*)(bias + n);
                float vx = acc[mt][nt][2 * h]     + bsv.x;
                float vy = acc[mt][nt][2 * h + 1] + bsv.y;
                if (EPI == EPI_PROJ) {
                    size_t dst = dstrow * CDIM + n;
                    float2 xv = *(const float2*)(extra + dst);
                    float2 v; v.x = vx + xv.x; v.y = vy + xv.y;
                    *(float2*)(outf + dst) = v;
                } else if (EPI == EPI_FC1) {
                    __nv_bfloat162 p(__float2bfloat16(gelu_exact(vx)),
                                     __float2bfloat16(gelu_exact(vy)));
                    *(__nv_bfloat162*)(outb + (size_t)r * HID + n) = p;
                } else {
                    float2 xv = *(const float2*)(outf + (size_t)r * CDIM + n);
                    float2 v; v.x = vx + xv.x; v.y = vy + xv.y;
                    *(float2*)(outf + (size_t)r * CDIM + n) = v;
                }
            }
        }
    }
}

// ---------------- tensor-core window attention (fused-table softmax) ---------
__global__ void __launch_bounds__(128) attn_tc()
{
    __shared__ uint32_t sm[1280 + 1280 + 1152 + 2304];
    constexpr int QS = 0, KS = 1280, VT = 2560, PS = 3712;

    const int blk = blockIdx.x;
    const int w = blk / HEADS, h = blk - w * HEADS;
    const int t = threadIdx.x, lane = t & 31, w4 = t >> 5;
    const int gid = lane >> 2, tig = lane & 3;

    char* smc = (char*)sm;
    const __nv_bfloat16* base = g_qkv + (size_t)w * NTOK * QKVC + (size_t)h * HD;

    for (int e = t; e < NTOK * 4; e += 128) {
        int n = e >> 2, s = e & 3;
        const char* rp = (const char*)(base + (size_t)n * QKVC) + s * 16;
        *(uint4*)(smc + QS * 4 + n * 80 + s * 16) = *(const uint4*)rp;
        *(uint4*)(smc + KS * 4 + n * 80 + s * 16) = *(const uint4*)(rp + CDIM * 2);
    }
    for (int e = t; e < 15 * 4; e += 128) {
        int n = 49 + (e >> 2), s = e & 3;
        uint4 z = {0, 0, 0, 0};
        *(uint4*)(smc + QS * 4 + n * 80 + s * 16) = z;
        *(uint4*)(smc + KS * 4 + n * 80 + s * 16) = z;
    }
    for (int e = t; e < NTOK * HD; e += 128) {
        int n = e >> 5, d = e & 31;
        ((__nv_bfloat16*)(smc + VT * 4 + d * 144))[n] = base[(size_t)n * QKVC + 2 * CDIM + d];
    }
    for (int e = t; e < HD * 15; e += 128) {
        int d = e / 15, n = 49 + e % 15;
        ((__nv_bfloat16*)(smc + VT * 4 + d * 144))[n] = __nv_bfloat16(0.f);
    }
    __syncthreads();

    const uint32_t smb = (uint32_t)__cvta_generic_to_shared(sm);
    const uint32_t aQ = smb + QS * 4 + (w4 * 16 + (lane & 15)) * 80 + (lane >> 4) * 16;
    const uint32_t bK = smb + KS * 4 +
        ((lane & 7) + ((lane & 16) >> 1)) * 80 + ((lane >> 3) & 1) * 16;
    float acc[8][4];
#pragma unroll
    for (int i = 0; i < 8; i++)
#pragma unroll
        for (int j = 0; j < 4; j++) acc[i][j] = 0.f;
#pragma unroll
    for (int kk = 0; kk < 2; kk++) {
        uint32_t a[4]; ldsm4(a, aQ + kk * 32);
#pragma unroll
        for (int ntp = 0; ntp < 4; ntp++) {
            uint32_t b[4]; ldsm4(b, bK + ntp * 1280u + kk * 32);
            mma_bf(acc[2 * ntp],     a, b[0], b[1]);
            mma_bf(acc[2 * ntp + 1], a, b[2], b[3]);
        }
    }

    const int wi = w & 63;
    const int cls = (((wi >> 3) == 7) ? 2 : 0) | (((wi & 7) == 7) ? 1 : 0);
    const float* tabh = g_tab + (size_t)(cls * HEADS + h) * NTOK * 64;

    const float scale = 0.17677669529663688f;
#pragma unroll
    for (int rr = 0; rr < 2; rr++) {
        int r = w4 * 16 + gid + rr * 8;
        const bool rv = (r < NTOK);
        const float* trow = tabh + (size_t)(rv ? r : 0) * 64 + tig * 2;
        float vv[16]; float mx = -1e30f;
#pragma unroll
        for (int nt = 0; nt < 8; nt++) {
            float2 tv = *(const float2*)(trow + nt * 8);
            float v0 = rv ? acc[nt][2 * rr]     * scale + tv.x : -1e30f;
            float v1 = rv ? acc[nt][2 * rr + 1] * scale + tv.y : -1e30f;
            vv[2 * nt] = v0; vv[2 * nt + 1] = v1;
            mx = fmaxf(mx, fmaxf(v0, v1));
        }
        mx = fmaxf(mx, __shfl_xor_sync(0xffffffffu, mx, 1));
        mx = fmaxf(mx, __shfl_xor_sync(0xffffffffu, mx, 2));
        float sum = 0.f;
#pragma unroll
        for (int i = 0; i < 16; i++) { vv[i] = __expf(vv[i] - mx); sum += vv[i]; }
        sum += __shfl_xor_sync(0xffffffffu, sum, 1);
        sum += __shfl_xor_sync(0xffffffffu, sum, 2);
        float inv = 1.0f / sum;
#pragma unroll
        for (int nt = 0; nt < 8; nt++) {
            int c = nt * 8 + tig * 2;
            __nv_bfloat162 p(__float2bfloat16(vv[2 * nt] * inv),
                             __float2bfloat16(vv[2 * nt + 1] * inv));
            *(__nv_bfloat162*)(smc + PS * 4 + r * 144 + c * 2) = p;
        }
    }
    __syncwarp();

    const uint32_t aP = smb + PS * 4 + (w4 * 16 + (lane & 15)) * 144 + (lane >> 4) * 16;
    const uint32_t bV = smb + VT * 4 +
        ((lane & 7) + ((lane & 16) >> 1)) * 144 + ((lane >> 3) & 1) * 16;
    float oa[4][4];
#pragma unroll
    for (int i = 0; i < 4; i++)
#pragma unroll
        for (int j = 0; j < 4; j++) oa[i][j] = 0.f;
#pragma unroll
    for (int ks = 0; ks < 4; ks++) {
        uint32_t a[4]; ldsm4(a, aP + ks * 32);
        uint32_t b0[4], b1[4];
        ldsm4(b0, bV + ks * 32);
        ldsm4(b1, bV + 16 * 144 + ks * 32);
        mma_bf(oa[0], a, b0[0], b0[1]);
        mma_bf(oa[1], a, b0[2], b0[3]);
        mma_bf(oa[2], a, b1[0], b1[1]);
        mma_bf(oa[3], a, b1[2], b1[3]);
    }
    __nv_bfloat16* ob = g_att + (size_t)w * NTOK * CDIM + (size_t)h * HD;
#pragma unroll
    for (int rr = 0; rr < 2; rr++) {
        int r = w4 * 16 + gid + rr * 8;
        if (r < NTOK) {
#pragma unroll
            for (int nt = 0; nt < 4; nt++) {
                int c = nt * 8 + tig * 2;
                __nv_bfloat162 p(__float2bfloat16(oa[nt][2 * rr]),
                                 __float2bfloat16(oa[nt][2 * rr + 1]));
                *(__nv_bfloat162*)(ob + (size_t)r * CDIM + c) = p;
            }
        }
    }
}

// ---------------- launch ----------------------------------------------------
extern "C" void kernel_launch(void* const* d_in, const int* in_sizes, int n_in,
                              void* d_out, int out_size)
{
    const float* x      = (const float*)d_in[0];
    const float* n1g    = (const float*)d_in[1];
    const float* n1b    = (const float*)d_in[2];
    const float* qkv_w  = (const float*)d_in[3];
    const float* qkv_b  = (const float*)d_in[4];
    const float* relb   = (const float*)d_in[5];
    const float* proj_w = (const float*)d_in[6];
    const float* proj_b = (const float*)d_in[7];
    const float* n2g    = (const float*)d_in[8];
    const float* n2b    = (const float*)d_in[9];
    const float* fc1_w  = (const float*)d_in[10];
    const float* fc1_b  = (const float*)d_in[11];
    const float* fc2_w  = (const float*)d_in[12];
    const float* fc2_b  = (const float*)d_in[13];
    float* out = (float*)d_out;

    __nv_bfloat16 *pxw, *pqkv, *patt, *phid, *pwqkv, *pwproj, *pwfc1, *pwfc2;
    cudaGetSymbolAddress((void**)&pxw,   g_xw);
    cudaGetSymbolAddress((void**)&pqkv,  g_qkv);
    cudaGetSymbolAddress((void**)&patt,  g_att);
    cudaGetSymbolAddress((void**)&phid,  g_hid);
    cudaGetSymbolAddress((void**)&pwqkv, g_wqkv);
    cudaGetSymbolAddress((void**)&pwproj,g_wproj);
    cudaGetSymbolAddress((void**)&pwfc1, g_wfc1);
    cudaGetSymbolAddress((void**)&pwfc2, g_wfc2);

    const int LN_BLOCKS = (int)(ROWS / 8);       // 25088
    const int MB = (int)(ROWS / 128);            // 1568
    constexpr int WTOT = QKVC * CDIM + CDIM * CDIM + HID * CDIM + CDIM * HID;

    w2bf_all<<<(WTOT + 255) / 256, 256>>>(qkv_w, proj_w, fc1_w, fc2_w,
                                          pwqkv, pwproj, pwfc1, pwfc2);
    tab_kernel<<<4 * HEADS, 256>>>(relb);

    ln_kernel<true><<<LN_BLOCKS, 256>>>(x, n1g, n1b);
    gemm_bf96<192, EPI_QKV><<<dim3(QKVC / 96, MB), 128>>>(pxw, pwqkv, qkv_b, nullptr, pqkv, nullptr);
    attn_tc<<<NWIN * HEADS, 128>>>();
    gemm_bf64<192, EPI_PROJ><<<dim3(CDIM / 64, MB), 128>>>(patt, pwproj, proj_b, out, nullptr, x);
    ln_kernel<false><<<LN_BLOCKS, 256>>>(out, n2g, n2b);
    gemm_bf64<192, EPI_FC1><<<dim3(HID / 64, MB), 128>>>(pxw, pwfc1, fc1_b, nullptr, phid, nullptr);
    gemm_bf64<768, EPI_FC2><<<dim3(CDIM / 64, MB), 128>>>(phid, pwfc2, fc2_b, out, nullptr, nullptr);
}

// round 11
// speedup vs baseline: 1.1193x; 1.0024x over previous
#include <cuda_runtime.h>
#include <cuda_bf16.h>
#include <math.h>
#include <stdint.h>

// ---------------- problem constants ----------------
constexpr int BATCH = 64, HIMG = 56, WIMG = 56, CDIM = 192;
constexpr int HEADS = 6, HD = 32, WSZ = 7, SSZ = 3, NWG = 8, NTOK = 49;
constexpr int NWIN = BATCH * NWG * NWG;          // 4096
constexpr size_t ROWS = (size_t)NWIN * NTOK;     // 200704
constexpr int HID = 768, QKVC = 576;

// ---------------- scratch ----------------
__device__ __nv_bfloat16 g_xw [ROWS * CDIM];
__device__ __nv_bfloat16 g_qkv[ROWS * QKVC];
__device__ __nv_bfloat16 g_att[ROWS * CDIM];
__device__ __nv_bfloat16 g_hid[ROWS * HID];
__device__ __nv_bfloat16 g_wqkv[QKVC * CDIM];
__device__ __nv_bfloat16 g_wproj[CDIM * CDIM];
__device__ __nv_bfloat16 g_wfc1[HID * CDIM];
__device__ __nv_bfloat16 g_wfc2[CDIM * HID];
__device__ float g_tab[4 * HEADS * NTOK * 64];   // fused bias+mask, padded cols

// ---------------- helpers ----------------
__device__ __forceinline__ void ldsm4(uint32_t* r, uint32_t addr) {
    asm volatile("ldmatrix.sync.aligned.m8n8.x4.shared.b16 {%0,%1,%2,%3}, [%4];"
        : "=r"(r[0]), "=r"(r[1]), "=r"(r[2]), "=r"(r[3]) : "r"(addr));
}
__device__ __forceinline__ void mma_bf(float* c, const uint32_t* a, uint32_t b0, uint32_t b1) {
    asm volatile(
        "mma.sync.aligned.m16n8k16.row.col.f32.bf16.bf16.f32 "
        "{%0,%1,%2,%3}, {%4,%5,%6,%7}, {%8,%9}, {%0,%1,%2,%3};"
        : "+f"(c[0]), "+f"(c[1]), "+f"(c[2]), "+f"(c[3])
        : "r"(a[0]), "r"(a[1]), "r"(a[2]), "r"(a[3]), "r"(b0), "r"(b1));
}
__device__ __forceinline__ void cpa16ca(uint32_t dst, const void* src) {
    asm volatile("cp.async.ca.shared.global [%0], [%1], 16;" :: "r"(dst), "l"(src));
}
__device__ __forceinline__ void cpa16cg(uint32_t dst, const void* src) {
    asm volatile("cp.async.cg.shared.global [%0], [%1], 16;" :: "r"(dst), "l"(src));
}
__device__ __forceinline__ void cpcommit() { asm volatile("cp.async.commit_group;"); }
template<int N> __device__ __forceinline__ void cpwait() {
    asm volatile("cp.async.wait_group %0;" :: "n"(N));
}
__device__ __forceinline__ float gelu_exact(float v) {
    return 0.5f * v * (1.0f + erff(v * 0.70710678118654752f));
}

// ---------------- fused weight conversion ----------------
__global__ void w2bf_all(const float* __restrict__ s0, const float* __restrict__ s1,
                         const float* __restrict__ s2, const float* __restrict__ s3,
                         __nv_bfloat16* __restrict__ d0, __nv_bfloat16* __restrict__ d1,
                         __nv_bfloat16* __restrict__ d2, __nv_bfloat16* __restrict__ d3)
{
    constexpr int N0 = QKVC * CDIM, N1 = CDIM * CDIM, N2 = HID * CDIM, N3 = CDIM * HID;
    int i = blockIdx.x * blockDim.x + threadIdx.x;
    if (i < N0) d0[i] = __float2bfloat16(s0[i]);
    int j = i - N0;
    if (j >= 0 && j < N1) d1[j] = __float2bfloat16(s1[j]);
    int k = j - N1;
    if (k >= 0 && k < N2) d2[k] = __float2bfloat16(s2[k]);
    int l = k - N2;
    if (l >= 0 && l < N3) d3[l] = __float2bfloat16(s3[l]);
}

// ---------------- fused bias+mask table: [cls][head][49][64] ----------------
__global__ void tab_kernel(const float* __restrict__ bias_table)
{
    const int cls = blockIdx.x / HEADS, h = blockIdx.x % HEADS;
    float* tp = g_tab + (size_t)blockIdx.x * NTOK * 64;
    for (int e = threadIdx.x; e < NTOK * 64; e += blockDim.x) {
        int n = e >> 6, m = e & 63;
        float v;
        if (m < NTOK) {
            int i1 = n / WSZ, j1 = n - i1 * WSZ;
            int i2 = m / WSZ, j2 = m - i2 * WSZ;
            int idx = (i1 - i2 + WSZ - 1) * (2 * WSZ - 1) + (j1 - j2 + WSZ - 1);
            int rh1 = (cls & 2) ? (i1 < 4 ? 1 : 2) : 0;
            int rw1 = (cls & 1) ? (j1 < 4 ? 1 : 2) : 0;
            int rh2 = (cls & 2) ? (i2 < 4 ? 1 : 2) : 0;
            int rw2 = (cls & 1) ? (j2 < 4 ? 1 : 2) : 0;
            float msk = (rh1 * 3 + rw1 == rh2 * 3 + rw2) ? 0.f : -100.f;
            v = bias_table[idx * HEADS + h] + msk;
        } else {
            v = -30000.f;
        }
        tp[e] = v;
    }
}

// ---------------- LayerNorm (+ optional shift/window gather), bf16 out ------
template<bool WIN>
__global__ void __launch_bounds__(256) ln_kernel(const float* __restrict__ x,
                                                 const float* __restrict__ gg,
                                                 const float* __restrict__ bb)
{
    int warp = (blockIdx.x << 3) + (threadIdx.x >> 5);
    int lane = threadIdx.x & 31;
    size_t src;
    if (WIN) {
        int w = warp / NTOK, n = warp - w * NTOK;
        int bi = w >> 6, wi = w & 63, wh = wi >> 3, ww = wi & 7;
        int ii = n / WSZ, jj = n - ii * WSZ;
        int hs = wh * WSZ + ii + SSZ; if (hs >= HIMG) hs -= HIMG;
        int ws_ = ww * WSZ + jj + SSZ; if (ws_ >= WIMG) ws_ -= WIMG;
        src = ((size_t)bi * (HIMG * WIMG) + (size_t)hs * WIMG + ws_) * CDIM;
    } else {
        src = (size_t)warp * CDIM;
    }
    const float* xr = x + src;
    float v[6]; float s = 0.f;
#pragma unroll
    for (int t = 0; t < 6; t++) { v[t] = xr[lane + 32 * t]; s += v[t]; }
#pragma unroll
    for (int o = 16; o; o >>= 1) s += __shfl_xor_sync(0xffffffffu, s, o);
    float mu = s * (1.0f / CDIM);
    float vs = 0.f;
#pragma unroll
    for (int t = 0; t < 6; t++) { float d = v[t] - mu; vs += d * d; }
#pragma unroll
    for (int o = 16; o; o >>= 1) vs += __shfl_xor_sync(0xffffffffu, vs, o);
    float inv = rsqrtf(vs * (1.0f / CDIM) + 1e-5f);
    __nv_bfloat16* op = g_xw + (size_t)warp * CDIM;
#pragma unroll
    for (int t = 0; t < 6; t++) {
        int c = lane + 32 * t;
        op[c] = __float2bfloat16((v[t] - mu) * inv * gg[c] + bb[c]);
    }
}

enum { EPI_QKV = 0, EPI_PROJ = 1, EPI_FC1 = 2, EPI_FC2 = 3 };

// ---------------- GEMM A: BM=128, BN=96 (.cg) — QKV + FC1 -------------------
template<int KD, int EPI>
__global__ void __launch_bounds__(128) gemm_bf96(
    const __nv_bfloat16* __restrict__ A, const __nv_bfloat16* __restrict__ Wm,
    const float* __restrict__ bias,
    __nv_bfloat16* __restrict__ outb)
{
    __shared__ uint32_t sm[2 * 2560 + 2 * 1920];
    constexpr uint32_t ABUF = 10240u, BBUF = 7680u, BOFF = 2 * ABUF;
    constexpr int STR = (EPI == EPI_QKV) ? QKVC : HID;
    const int t = threadIdx.x, lane = t & 31, w4 = t >> 5;
    const int warpM = w4 & 1, warpN = w4 >> 1;
    const int m0 = blockIdx.y * 128, n0 = blockIdx.x * 96;
    const int gid = lane >> 2, tig = lane & 3;
    const int lr = t >> 2, seg = t & 3;

    const __nv_bfloat16* Ap = A  + (size_t)(m0 + lr) * KD + seg * 8;
    const __nv_bfloat16* Bp = Wm + (size_t)(n0 + lr) * KD + seg * 8;
    const uint32_t smb = (uint32_t)__cvta_generic_to_shared(sm);
    const uint32_t aSt = smb + (uint32_t)((lr * 20 + seg * 4) * 4);
    const uint32_t bSt = smb + BOFF + (uint32_t)((lr * 20 + seg * 4) * 4);

    auto issue = [&](int buf, int k0) {
#pragma unroll
        for (int p = 0; p < 4; p++)
            cpa16cg(aSt + buf * ABUF + p * 2560u, Ap + (size_t)p * 32 * KD + k0);
#pragma unroll
        for (int q = 0; q < 3; q++)
            cpa16cg(bSt + buf * BBUF + q * 2560u, Bp + (size_t)q * 32 * KD + k0);
        cpcommit();
    };

    const uint32_t aRd = smb + (uint32_t)(((warpM * 64 + (lane & 15)) * 80) + (lane >> 4) * 16);
    const uint32_t bRd = smb + BOFF +
        (uint32_t)(((warpN * 48 + (lane & 7) + ((lane & 16) >> 1)) * 80) + ((lane >> 3) & 1) * 16);

    float acc[4][6][4];
#pragma unroll
    for (int i = 0; i < 4; i++)
#pragma unroll
        for (int j = 0; j < 6; j++)
#pragma unroll
            for (int r = 0; r < 4; r++) acc[i][j][r] = 0.f;

    constexpr int NIT = KD / 32;
    issue(0, 0);
    for (int it = 0; it < NIT; ++it) {
        const int cur = it & 1;
        cpwait<0>();
        __syncthreads();
        if (it + 1 < NIT) issue(cur ^ 1, (it + 1) * 32);
        const uint32_t aO = aRd + cur * ABUF;
        const uint32_t bO = bRd + cur * BBUF;
#pragma unroll
        for (int kk = 0; kk < 2; kk++) {
            uint32_t a[4][4], b[3][4];
#pragma unroll
            for (int mt = 0; mt < 4; mt++) ldsm4(a[mt], aO + mt * 1280u + kk * 32);
#pragma unroll
            for (int g = 0; g < 3; g++) ldsm4(b[g], bO + g * 1280u + kk * 32);
#pragma unroll
            for (int mt = 0; mt < 4; mt++)
#pragma unroll
                for (int g = 0; g < 3; g++) {
                    mma_bf(acc[mt][2 * g],     a[mt], b[g][0], b[g][1]);
                    mma_bf(acc[mt][2 * g + 1], a[mt], b[g][2], b[g][3]);
                }
        }
        __syncthreads();
    }

    const int mbase = m0 + warpM * 64;
    const int nbase = n0 + warpN * 48;
#pragma unroll
    for (int mt = 0; mt < 4; mt++) {
#pragma unroll
        for (int h = 0; h < 2; h++) {
            int r = mbase + mt * 16 + gid + h * 8;
#pragma unroll
            for (int nt = 0; nt < 6; nt++) {
                int n = nbase + nt * 8 + tig * 2;
                float2 bsv = *(const float2*)(bias + n);
                float vx = acc[mt][nt][2 * h]     + bsv.x;
                float vy = acc[mt][nt][2 * h + 1] + bsv.y;
                if (EPI == EPI_FC1) { vx = gelu_exact(vx); vy = gelu_exact(vy); }
                __nv_bfloat162 p(__float2bfloat16(vx), __float2bfloat16(vy));
                *(__nv_bfloat162*)(outb + (size_t)r * STR + n) = p;
            }
        }
    }
}

// ---------------- GEMM B: BM=128, BN=64 (.ca) — proj/fc2 --------------------
template<int KD, int EPI>
__global__ void __launch_bounds__(128) gemm_bf64(
    const __nv_bfloat16* __restrict__ A, const __nv_bfloat16* __restrict__ Wm,
    const float* __restrict__ bias, float* __restrict__ outf,
    const float* __restrict__ extra)
{
    __shared__ uint32_t sm[2 * 2560 + 2 * 1280];
    const int t = threadIdx.x, lane = t & 31, w4 = t >> 5;
    const int warpM = w4 & 1, warpN = w4 >> 1;
    const int m0 = blockIdx.y * 128, n0 = blockIdx.x * 64;
    const int gid = lane >> 2, tig = lane & 3;
    const int lr = t >> 2, seg = t & 3;

    const __nv_bfloat16* Ap = A  + (size_t)(m0 + lr) * KD + seg * 8;
    const __nv_bfloat16* Bp = Wm + (size_t)(n0 + lr) * KD + seg * 8;
    const uint32_t smb = (uint32_t)__cvta_generic_to_shared(sm);
    const uint32_t aSt = smb + (uint32_t)((lr * 20 + seg * 4) * 4);
    const uint32_t bSt = smb + 20480u + (uint32_t)((lr * 20 + seg * 4) * 4);

    auto issue = [&](int buf, int k0) {
#pragma unroll
        for (int p = 0; p < 4; p++)
            cpa16ca(aSt + buf * 10240u + p * 2560u, Ap + (size_t)p * 32 * KD + k0);
#pragma unroll
        for (int q = 0; q < 2; q++)
            cpa16ca(bSt + buf * 5120u + q * 2560u, Bp + (size_t)q * 32 * KD + k0);
        cpcommit();
    };

    const uint32_t aRd = smb + (uint32_t)(((warpM * 64 + (lane & 15)) * 80) + (lane >> 4) * 16);
    const uint32_t bRd = smb + 20480u +
        (uint32_t)(((warpN * 32 + (lane & 7) + ((lane & 16) >> 1)) * 80) + ((lane >> 3) & 1) * 16);

    float acc[4][4][4];
#pragma unroll
    for (int i = 0; i < 4; i++)
#pragma unroll
        for (int j = 0; j < 4; j++)
#pragma unroll
            for (int r = 0; r < 4; r++) acc[i][j][r] = 0.f;

    constexpr int NIT = KD / 32;
    issue(0, 0);
    for (int it = 0; it < NIT; ++it) {
        const int cur = it & 1;
        cpwait<0>();
        __syncthreads();
        if (it + 1 < NIT) issue(cur ^ 1, (it + 1) * 32);
        const uint32_t aO = aRd + cur * 10240u;
        const uint32_t bO = bRd + cur * 5120u;
#pragma unroll
        for (int kk = 0; kk < 2; kk++) {
            uint32_t a[4][4], b0[4], b1[4];
#pragma unroll
            for (int mt = 0; mt < 4; mt++) ldsm4(a[mt], aO + mt * 1280u + kk * 32);
            ldsm4(b0, bO + kk * 32);
            ldsm4(b1, bO + 1280u + kk * 32);
#pragma unroll
            for (int mt = 0; mt < 4; mt++) {
                mma_bf(acc[mt][0], a[mt], b0[0], b0[1]);
                mma_bf(acc[mt][1], a[mt], b0[2], b0[3]);
                mma_bf(acc[mt][2], a[mt], b1[0], b1[1]);
                mma_bf(acc[mt][3], a[mt], b1[2], b1[3]);
            }
        }
        __syncthreads();
    }

    const int mbase = m0 + warpM * 64;
    const int nbase = n0 + warpN * 32;
#pragma unroll
    for (int mt = 0; mt < 4; mt++) {
#pragma unroll
        for (int h = 0; h < 2; h++) {
            int r = mbase + mt * 16 + gid + h * 8;
            size_t dstrow = 0;
            if (EPI == EPI_PROJ) {
                int w = r / NTOK, n = r - w * NTOK;
                int bi = w >> 6, wi = w & 63, wh = wi >> 3, ww = wi & 7;
                int ii = n / WSZ, jj = n - ii * WSZ;
                int hp = wh * WSZ + ii + SSZ; if (hp >= HIMG) hp -= HIMG;
                int wp = ww * WSZ + jj + SSZ; if (wp >= WIMG) wp -= WIMG;
                dstrow = ((size_t)bi * (HIMG * WIMG) + (size_t)hp * WIMG + wp);
            }
#pragma unroll
            for (int nt = 0; nt < 4; nt++) {
                int n = nbase + nt * 8 + tig * 2;
                float2 bsv = *(const float2*)(bias + n);
                float vx = acc[mt][nt][2 * h]     + bsv.x;
                float vy = acc[mt][nt][2 * h + 1] + bsv.y;
                if (EPI == EPI_PROJ) {
                    size_t dst = dstrow * CDIM + n;
                    float2 xv = *(const float2*)(extra + dst);
                    float2 v; v.x = vx + xv.x; v.y = vy + xv.y;
                    *(float2*)(outf + dst) = v;
                } else { // EPI_FC2
                    float2 xv = *(const float2*)(outf + (size_t)r * CDIM + n);
                    float2 v; v.x = vx + xv.x; v.y = vy + xv.y;
                    *(float2*)(outf + (size_t)r * CDIM + n) = v;
                }
            }
        }
    }
}

// ---------------- tensor-core window attention (fused-table softmax) ---------
__global__ void __launch_bounds__(128) attn_tc()
{
    __shared__ uint32_t sm[1280 + 1280 + 1152 + 2304];
    constexpr int QS = 0, KS = 1280, VT = 2560, PS = 3712;

    const int blk = blockIdx.x;
    const int w = blk / HEADS, h = blk - w * HEADS;
    const int t = threadIdx.x, lane = t & 31, w4 = t >> 5;
    const int gid = lane >> 2, tig = lane & 3;

    char* smc = (char*)sm;
    const __nv_bfloat16* base = g_qkv + (size_t)w * NTOK * QKVC + (size_t)h * HD;

    for (int e = t; e < NTOK * 4; e += 128) {
        int n = e >> 2, s = e & 3;
        const char* rp = (const char*)(base + (size_t)n * QKVC) + s * 16;
        *(uint4*)(smc + QS * 4 + n * 80 + s * 16) = *(const uint4*)rp;
        *(uint4*)(smc + KS * 4 + n * 80 + s * 16) = *(const uint4*)(rp + CDIM * 2);
    }
    for (int e = t; e < 15 * 4; e += 128) {
        int n = 49 + (e >> 2), s = e & 3;
        uint4 z = {0, 0, 0, 0};
        *(uint4*)(smc + QS * 4 + n * 80 + s * 16) = z;
        *(uint4*)(smc + KS * 4 + n * 80 + s * 16) = z;
    }
    for (int e = t; e < NTOK * HD; e += 128) {
        int n = e >> 5, d = e & 31;
        ((__nv_bfloat16*)(smc + VT * 4 + d * 144))[n] = base[(size_t)n * QKVC + 2 * CDIM + d];
    }
    for (int e = t; e < HD * 15; e += 128) {
        int d = e / 15, n = 49 + e % 15;
        ((__nv_bfloat16*)(smc + VT * 4 + d * 144))[n] = __nv_bfloat16(0.f);
    }
    __syncthreads();

    const uint32_t smb = (uint32_t)__cvta_generic_to_shared(sm);
    const uint32_t aQ = smb + QS * 4 + (w4 * 16 + (lane & 15)) * 80 + (lane >> 4) * 16;
    const uint32_t bK = smb + KS * 4 +
        ((lane & 7) + ((lane & 16) >> 1)) * 80 + ((lane >> 3) & 1) * 16;
    float acc[8][4];
#pragma unroll
    for (int i = 0; i < 8; i++)
#pragma unroll
        for (int j = 0; j < 4; j++) acc[i][j] = 0.f;
#pragma unroll
    for (int kk = 0; kk < 2; kk++) {
        uint32_t a[4]; ldsm4(a, aQ + kk * 32);
#pragma unroll
        for (int ntp = 0; ntp < 4; ntp++) {
            uint32_t b[4]; ldsm4(b, bK + ntp * 1280u + kk * 32);
            mma_bf(acc[2 * ntp],     a, b[0], b[1]);
            mma_bf(acc[2 * ntp + 1], a, b[2], b[3]);
        }
    }

    const int wi = w & 63;
    const int cls = (((wi >> 3) == 7) ? 2 : 0) | (((wi & 7) == 7) ? 1 : 0);
    const float* tabh = g_tab + (size_t)(cls * HEADS + h) * NTOK * 64;

    const float scale = 0.17677669529663688f;
#pragma unroll
    for (int rr = 0; rr < 2; rr++) {
        int r = w4 * 16 + gid + rr * 8;
        const bool rv = (r < NTOK);
        const float* trow = tabh + (size_t)(rv ? r : 0) * 64 + tig * 2;
        float vv[16]; float mx = -1e30f;
#pragma unroll
        for (int nt = 0; nt < 8; nt++) {
            float2 tv = *(const float2*)(trow + nt * 8);
            float v0 = rv ? acc[nt][2 * rr]     * scale + tv.x : -1e30f;
            float v1 = rv ? acc[nt][2 * rr + 1] * scale + tv.y : -1e30f;
            vv[2 * nt] = v0; vv[2 * nt + 1] = v1;
            mx = fmaxf(mx, fmaxf(v0, v1));
        }
        mx = fmaxf(mx, __shfl_xor_sync(0xffffffffu, mx, 1));
        mx = fmaxf(mx, __shfl_xor_sync(0xffffffffu, mx, 2));
        float sum = 0.f;
#pragma unroll
        for (int i = 0; i < 16; i++) { vv[i] = __expf(vv[i] - mx); sum += vv[i]; }
        sum += __shfl_xor_sync(0xffffffffu, sum, 1);
        sum += __shfl_xor_sync(0xffffffffu, sum, 2);
        float inv = 1.0f / sum;
#pragma unroll
        for (int nt = 0; nt < 8; nt++) {
            int c = nt * 8 + tig * 2;
            __nv_bfloat162 p(__float2bfloat16(vv[2 * nt] * inv),
                             __float2bfloat16(vv[2 * nt + 1] * inv));
            *(__nv_bfloat162*)(smc + PS * 4 + r * 144 + c * 2) = p;
        }
    }
    __syncwarp();

    const uint32_t aP = smb + PS * 4 + (w4 * 16 + (lane & 15)) * 144 + (lane >> 4) * 16;
    const uint32_t bV = smb + VT * 4 +
        ((lane & 7) + ((lane & 16) >> 1)) * 144 + ((lane >> 3) & 1) * 16;
    float oa[4][4];
#pragma unroll
    for (int i = 0; i < 4; i++)
#pragma unroll
        for (int j = 0; j < 4; j++) oa[i][j] = 0.f;
#pragma unroll
    for (int ks = 0; ks < 4; ks++) {
        uint32_t a[4]; ldsm4(a, aP + ks * 32);
        uint32_t b0[4], b1[4];
        ldsm4(b0, bV + ks * 32);
        ldsm4(b1, bV + 16 * 144 + ks * 32);
        mma_bf(oa[0], a, b0[0], b0[1]);
        mma_bf(oa[1], a, b0[2], b0[3]);
        mma_bf(oa[2], a, b1[0], b1[1]);
        mma_bf(oa[3], a, b1[2], b1[3]);
    }
    __nv_bfloat16* ob = g_att + (size_t)w * NTOK * CDIM + (size_t)h * HD;
#pragma unroll
    for (int rr = 0; rr < 2; rr++) {
        int r = w4 * 16 + gid + rr * 8;
        if (r < NTOK) {
#pragma unroll
            for (int nt = 0; nt < 4; nt++) {
                int c = nt * 8 + tig * 2;
                __nv_bfloat162 p(__float2bfloat16(oa[nt][2 * rr]),
                                 __float2bfloat16(oa[nt][2 * rr + 1]));
                *(__nv_bfloat162*)(ob + (size_t)r * CDIM + c) = p;
            }
        }
    }
}

// ---------------- launch ----------------------------------------------------
extern "C" void kernel_launch(void* const* d_in, const int* in_sizes, int n_in,
                              void* d_out, int out_size)
{
    const float* x      = (const float*)d_in[0];
    const float* n1g    = (const float*)d_in[1];
    const float* n1b    = (const float*)d_in[2];
    const float* qkv_w  = (const float*)d_in[3];
    const float* qkv_b  = (const float*)d_in[4];
    const float* relb   = (const float*)d_in[5];
    const float* proj_w = (const float*)d_in[6];
    const float* proj_b = (const float*)d_in[7];
    const float* n2g    = (const float*)d_in[8];
    const float* n2b    = (const float*)d_in[9];
    const float* fc1_w  = (const float*)d_in[10];
    const float* fc1_b  = (const float*)d_in[11];
    const float* fc2_w  = (const float*)d_in[12];
    const float* fc2_b  = (const float*)d_in[13];
    float* out = (float*)d_out;

    __nv_bfloat16 *pxw, *pqkv, *patt, *phid, *pwqkv, *pwproj, *pwfc1, *pwfc2;
    cudaGetSymbolAddress((void**)&pxw,   g_xw);
    cudaGetSymbolAddress((void**)&pqkv,  g_qkv);
    cudaGetSymbolAddress((void**)&patt,  g_att);
    cudaGetSymbolAddress((void**)&phid,  g_hid);
    cudaGetSymbolAddress((void**)&pwqkv, g_wqkv);
    cudaGetSymbolAddress((void**)&pwproj,g_wproj);
    cudaGetSymbolAddress((void**)&pwfc1, g_wfc1);
    cudaGetSymbolAddress((void**)&pwfc2, g_wfc2);

    const int LN_BLOCKS = (int)(ROWS / 8);       // 25088
    const int MB = (int)(ROWS / 128);            // 1568
    constexpr int WTOT = QKVC * CDIM + CDIM * CDIM + HID * CDIM + CDIM * HID;

    w2bf_all<<<(WTOT + 255) / 256, 256>>>(qkv_w, proj_w, fc1_w, fc2_w,
                                          pwqkv, pwproj, pwfc1, pwfc2);
    tab_kernel<<<4 * HEADS, 256>>>(relb);

    ln_kernel<true><<<LN_BLOCKS, 256>>>(x, n1g, n1b);
    gemm_bf96<192, EPI_QKV><<<dim3(QKVC / 96, MB), 128>>>(pxw, pwqkv, qkv_b, pqkv);
    attn_tc<<<NWIN * HEADS, 128>>>();
    gemm_bf64<192, EPI_PROJ><<<dim3(CDIM / 64, MB), 128>>>(patt, pwproj, proj_b, out, x);
    ln_kernel<false><<<LN_BLOCKS, 256>>>(out, n2g, n2b);
    gemm_bf96<192, EPI_FC1><<<dim3(HID / 96, MB), 128>>>(pxw, pwfc1, fc1_b, phid);
    gemm_bf64<768, EPI_FC2><<<dim3(CDIM / 64, MB), 128>>>(phid, pwfc2, fc2_b, out, nullptr);
}

// round 12
// speedup vs baseline: 1.1271x; 1.0070x over previous
#include <cuda_runtime.h>
#include <cuda_bf16.h>
#include <math.h>
#include <stdint.h>

// ---------------- problem constants ----------------
constexpr int BATCH = 64, HIMG = 56, WIMG = 56, CDIM = 192;
constexpr int HEADS = 6, HD = 32, WSZ = 7, SSZ = 3, NWG = 8, NTOK = 49;
constexpr int NWIN = BATCH * NWG * NWG;          // 4096
constexpr size_t ROWS = (size_t)NWIN * NTOK;     // 200704
constexpr int HID = 768, QKVC = 576;

// ---------------- scratch ----------------
__device__ __nv_bfloat16 g_xw [ROWS * CDIM];
__device__ __nv_bfloat16 g_qkv[ROWS * QKVC];
__device__ __nv_bfloat16 g_att[ROWS * CDIM];
__device__ __nv_bfloat16 g_hid[ROWS * HID];
__device__ __nv_bfloat16 g_wqkv[QKVC * CDIM];
__device__ __nv_bfloat16 g_wproj[CDIM * CDIM];
__device__ __nv_bfloat16 g_wfc1[HID * CDIM];
__device__ __nv_bfloat16 g_wfc2[CDIM * HID];
__device__ float g_tab[4 * HEADS * NTOK * 64];   // fused bias+mask, padded cols

// ---------------- helpers ----------------
__device__ __forceinline__ void ldsm4(uint32_t* r, uint32_t addr) {
    asm volatile("ldmatrix.sync.aligned.m8n8.x4.shared.b16 {%0,%1,%2,%3}, [%4];"
        : "=r"(r[0]), "=r"(r[1]), "=r"(r[2]), "=r"(r[3]) : "r"(addr));
}
__device__ __forceinline__ void mma_bf(float* c, const uint32_t* a, uint32_t b0, uint32_t b1) {
    asm volatile(
        "mma.sync.aligned.m16n8k16.row.col.f32.bf16.bf16.f32 "
        "{%0,%1,%2,%3}, {%4,%5,%6,%7}, {%8,%9}, {%0,%1,%2,%3};"
        : "+f"(c[0]), "+f"(c[1]), "+f"(c[2]), "+f"(c[3])
        : "r"(a[0]), "r"(a[1]), "r"(a[2]), "r"(a[3]), "r"(b0), "r"(b1));
}
__device__ __forceinline__ void cpa16ca(uint32_t dst, const void* src) {
    asm volatile("cp.async.ca.shared.global [%0], [%1], 16;" :: "r"(dst), "l"(src));
}
__device__ __forceinline__ void cpa16cg(uint32_t dst, const void* src) {
    asm volatile("cp.async.cg.shared.global [%0], [%1], 16;" :: "r"(dst), "l"(src));
}
__device__ __forceinline__ void cpcommit() { asm volatile("cp.async.commit_group;"); }
template<int N> __device__ __forceinline__ void cpwait() {
    asm volatile("cp.async.wait_group %0;" :: "n"(N));
}
__device__ __forceinline__ float gelu_exact(float v) {
    return 0.5f * v * (1.0f + erff(v * 0.70710678118654752f));
}

// ---------------- fused weight conversion ----------------
__global__ void w2bf_all(const float* __restrict__ s0, const float* __restrict__ s1,
                         const float* __restrict__ s2, const float* __restrict__ s3,
                         __nv_bfloat16* __restrict__ d0, __nv_bfloat16* __restrict__ d1,
                         __nv_bfloat16* __restrict__ d2, __nv_bfloat16* __restrict__ d3)
{
    constexpr int N0 = QKVC * CDIM, N1 = CDIM * CDIM, N2 = HID * CDIM, N3 = CDIM * HID;
    int i = blockIdx.x * blockDim.x + threadIdx.x;
    if (i < N0) d0[i] = __float2bfloat16(s0[i]);
    int j = i - N0;
    if (j >= 0 && j < N1) d1[j] = __float2bfloat16(s1[j]);
    int k = j - N1;
    if (k >= 0 && k < N2) d2[k] = __float2bfloat16(s2[k]);
    int l = k - N2;
    if (l >= 0 && l < N3) d3[l] = __float2bfloat16(s3[l]);
}

// ---------------- fused bias+mask table: [cls][head][49][64] ----------------
__global__ void tab_kernel(const float* __restrict__ bias_table)
{
    const int cls = blockIdx.x / HEADS, h = blockIdx.x % HEADS;
    float* tp = g_tab + (size_t)blockIdx.x * NTOK * 64;
    for (int e = threadIdx.x; e < NTOK * 64; e += blockDim.x) {
        int n = e >> 6, m = e & 63;
        float v;
        if (m < NTOK) {
            int i1 = n / WSZ, j1 = n - i1 * WSZ;
            int i2 = m / WSZ, j2 = m - i2 * WSZ;
            int idx = (i1 - i2 + WSZ - 1) * (2 * WSZ - 1) + (j1 - j2 + WSZ - 1);
            int rh1 = (cls & 2) ? (i1 < 4 ? 1 : 2) : 0;
            int rw1 = (cls & 1) ? (j1 < 4 ? 1 : 2) : 0;
            int rh2 = (cls & 2) ? (i2 < 4 ? 1 : 2) : 0;
            int rw2 = (cls & 1) ? (j2 < 4 ? 1 : 2) : 0;
            float msk = (rh1 * 3 + rw1 == rh2 * 3 + rw2) ? 0.f : -100.f;
            v = bias_table[idx * HEADS + h] + msk;
        } else {
            v = -30000.f;
        }
        tp[e] = v;
    }
}

// ---------------- LayerNorm (+ optional shift/window gather), bf16 out ------
template<bool WIN>
__global__ void __launch_bounds__(256) ln_kernel(const float* __restrict__ x,
                                                 const float* __restrict__ gg,
                                                 const float* __restrict__ bb)
{
    int warp = (blockIdx.x << 3) + (threadIdx.x >> 5);
    int lane = threadIdx.x & 31;
    size_t src;
    if (WIN) {
        int w = warp / NTOK, n = warp - w * NTOK;
        int bi = w >> 6, wi = w & 63, wh = wi >> 3, ww = wi & 7;
        int ii = n / WSZ, jj = n - ii * WSZ;
        int hs = wh * WSZ + ii + SSZ; if (hs >= HIMG) hs -= HIMG;
        int ws_ = ww * WSZ + jj + SSZ; if (ws_ >= WIMG) ws_ -= WIMG;
        src = ((size_t)bi * (HIMG * WIMG) + (size_t)hs * WIMG + ws_) * CDIM;
    } else {
        src = (size_t)warp * CDIM;
    }
    const float* xr = x + src;
    float v[6]; float s = 0.f;
#pragma unroll
    for (int t = 0; t < 6; t++) { v[t] = xr[lane + 32 * t]; s += v[t]; }
#pragma unroll
    for (int o = 16; o; o >>= 1) s += __shfl_xor_sync(0xffffffffu, s, o);
    float mu = s * (1.0f / CDIM);
    float vs = 0.f;
#pragma unroll
    for (int t = 0; t < 6; t++) { float d = v[t] - mu; vs += d * d; }
#pragma unroll
    for (int o = 16; o; o >>= 1) vs += __shfl_xor_sync(0xffffffffu, vs, o);
    float inv = rsqrtf(vs * (1.0f / CDIM) + 1e-5f);
    __nv_bfloat16* op = g_xw + (size_t)warp * CDIM;
#pragma unroll
    for (int t = 0; t < 6; t++) {
        int c = lane + 32 * t;
        op[c] = __float2bfloat16((v[t] - mu) * inv * gg[c] + bb[c]);
    }
}

enum { EPI_QKV = 0, EPI_PROJ = 1, EPI_FC1 = 2, EPI_FC2 = 3 };

// ---------------- GEMM A: BM=128, BN=96 (.cg) — QKV + FC1 -------------------
template<int KD, int EPI>
__global__ void __launch_bounds__(128) gemm_bf96(
    const __nv_bfloat16* __restrict__ A, const __nv_bfloat16* __restrict__ Wm,
    const float* __restrict__ bias,
    __nv_bfloat16* __restrict__ outb)
{
    __shared__ uint32_t sm[2 * 2560 + 2 * 1920];
    constexpr uint32_t ABUF = 10240u, BBUF = 7680u, BOFF = 2 * ABUF;
    constexpr int STR = (EPI == EPI_QKV) ? QKVC : HID;
    const int t = threadIdx.x, lane = t & 31, w4 = t >> 5;
    const int warpM = w4 & 1, warpN = w4 >> 1;
    const int m0 = blockIdx.y * 128, n0 = blockIdx.x * 96;
    const int gid = lane >> 2, tig = lane & 3;
    const int lr = t >> 2, seg = t & 3;

    const __nv_bfloat16* Ap = A  + (size_t)(m0 + lr) * KD + seg * 8;
    const __nv_bfloat16* Bp = Wm + (size_t)(n0 + lr) * KD + seg * 8;
    const uint32_t smb = (uint32_t)__cvta_generic_to_shared(sm);
    const uint32_t aSt = smb + (uint32_t)((lr * 20 + seg * 4) * 4);
    const uint32_t bSt = smb + BOFF + (uint32_t)((lr * 20 + seg * 4) * 4);

    auto issue = [&](int buf, int k0) {
#pragma unroll
        for (int p = 0; p < 4; p++)
            cpa16cg(aSt + buf * ABUF + p * 2560u, Ap + (size_t)p * 32 * KD + k0);
#pragma unroll
        for (int q = 0; q < 3; q++)
            cpa16cg(bSt + buf * BBUF + q * 2560u, Bp + (size_t)q * 32 * KD + k0);
        cpcommit();
    };

    const uint32_t aRd = smb + (uint32_t)(((warpM * 64 + (lane & 15)) * 80) + (lane >> 4) * 16);
    const uint32_t bRd = smb + BOFF +
        (uint32_t)(((warpN * 48 + (lane & 7) + ((lane & 16) >> 1)) * 80) + ((lane >> 3) & 1) * 16);

    float acc[4][6][4];
#pragma unroll
    for (int i = 0; i < 4; i++)
#pragma unroll
        for (int j = 0; j < 6; j++)
#pragma unroll
            for (int r = 0; r < 4; r++) acc[i][j][r] = 0.f;

    constexpr int NIT = KD / 32;
    issue(0, 0);
    for (int it = 0; it < NIT; ++it) {
        const int cur = it & 1;
        cpwait<0>();
        __syncthreads();
        if (it + 1 < NIT) issue(cur ^ 1, (it + 1) * 32);
        const uint32_t aO = aRd + cur * ABUF;
        const uint32_t bO = bRd + cur * BBUF;
#pragma unroll
        for (int kk = 0; kk < 2; kk++) {
            uint32_t a[4][4], b[3][4];
#pragma unroll
            for (int mt = 0; mt < 4; mt++) ldsm4(a[mt], aO + mt * 1280u + kk * 32);
#pragma unroll
            for (int g = 0; g < 3; g++) ldsm4(b[g], bO + g * 1280u + kk * 32);
#pragma unroll
            for (int mt = 0; mt < 4; mt++)
#pragma unroll
                for (int g = 0; g < 3; g++) {
                    mma_bf(acc[mt][2 * g],     a[mt], b[g][0], b[g][1]);
                    mma_bf(acc[mt][2 * g + 1], a[mt], b[g][2], b[g][3]);
                }
        }
        __syncthreads();
    }

    const int mbase = m0 + warpM * 64;
    const int nbase = n0 + warpN * 48;
#pragma unroll
    for (int mt = 0; mt < 4; mt++) {
#pragma unroll
        for (int h = 0; h < 2; h++) {
            int r = mbase + mt * 16 + gid + h * 8;
#pragma unroll
            for (int nt = 0; nt < 6; nt++) {
                int n = nbase + nt * 8 + tig * 2;
                float2 bsv = *(const float2*)(bias + n);
                float vx = acc[mt][nt][2 * h]     + bsv.x;
                float vy = acc[mt][nt][2 * h + 1] + bsv.y;
                if (EPI == EPI_FC1) { vx = gelu_exact(vx); vy = gelu_exact(vy); }
                __nv_bfloat162 p(__float2bfloat16(vx), __float2bfloat16(vy));
                *(__nv_bfloat162*)(outb + (size_t)r * STR + n) = p;
            }
        }
    }
}

// ---------------- GEMM B: BM=128, BN=64 (.ca) — proj/fc2 --------------------
template<int KD, int EPI>
__global__ void __launch_bounds__(128) gemm_bf64(
    const __nv_bfloat16* __restrict__ A, const __nv_bfloat16* __restrict__ Wm,
    const float* __restrict__ bias, float* __restrict__ outf,
    const float* __restrict__ extra)
{
    __shared__ uint32_t sm[2 * 2560 + 2 * 1280];
    const int t = threadIdx.x, lane = t & 31, w4 = t >> 5;
    const int warpM = w4 & 1, warpN = w4 >> 1;
    const int m0 = blockIdx.y * 128, n0 = blockIdx.x * 64;
    const int gid = lane >> 2, tig = lane & 3;
    const int lr = t >> 2, seg = t & 3;

    const __nv_bfloat16* Ap = A  + (size_t)(m0 + lr) * KD + seg * 8;
    const __nv_bfloat16* Bp = Wm + (size_t)(n0 + lr) * KD + seg * 8;
    const uint32_t smb = (uint32_t)__cvta_generic_to_shared(sm);
    const uint32_t aSt = smb + (uint32_t)((lr * 20 + seg * 4) * 4);
    const uint32_t bSt = smb + 20480u + (uint32_t)((lr * 20 + seg * 4) * 4);

    auto issue = [&](int buf, int k0) {
#pragma unroll
        for (int p = 0; p < 4; p++)
            cpa16ca(aSt + buf * 10240u + p * 2560u, Ap + (size_t)p * 32 * KD + k0);
#pragma unroll
        for (int q = 0; q < 2; q++)
            cpa16ca(bSt + buf * 5120u + q * 2560u, Bp + (size_t)q * 32 * KD + k0);
        cpcommit();
    };

    const uint32_t aRd = smb + (uint32_t)(((warpM * 64 + (lane & 15)) * 80) + (lane >> 4) * 16);
    const uint32_t bRd = smb + 20480u +
        (uint32_t)(((warpN * 32 + (lane & 7) + ((lane & 16) >> 1)) * 80) + ((lane >> 3) & 1) * 16);

    float acc[4][4][4];
#pragma unroll
    for (int i = 0; i < 4; i++)
#pragma unroll
        for (int j = 0; j < 4; j++)
#pragma unroll
            for (int r = 0; r < 4; r++) acc[i][j][r] = 0.f;

    constexpr int NIT = KD / 32;
    issue(0, 0);
    for (int it = 0; it < NIT; ++it) {
        const int cur = it & 1;
        cpwait<0>();
        __syncthreads();
        if (it + 1 < NIT) issue(cur ^ 1, (it + 1) * 32);
        const uint32_t aO = aRd + cur * 10240u;
        const uint32_t bO = bRd + cur * 5120u;
#pragma unroll
        for (int kk = 0; kk < 2; kk++) {
            uint32_t a[4][4], b0[4], b1[4];
#pragma unroll
            for (int mt = 0; mt < 4; mt++) ldsm4(a[mt], aO + mt * 1280u + kk * 32);
            ldsm4(b0, bO + kk * 32);
            ldsm4(b1, bO + 1280u + kk * 32);
#pragma unroll
            for (int mt = 0; mt < 4; mt++) {
                mma_bf(acc[mt][0], a[mt], b0[0], b0[1]);
                mma_bf(acc[mt][1], a[mt], b0[2], b0[3]);
                mma_bf(acc[mt][2], a[mt], b1[0], b1[1]);
                mma_bf(acc[mt][3], a[mt], b1[2], b1[3]);
            }
        }
        __syncthreads();
    }

    const int mbase = m0 + warpM * 64;
    const int nbase = n0 + warpN * 32;
#pragma unroll
    for (int mt = 0; mt < 4; mt++) {
#pragma unroll
        for (int h = 0; h < 2; h++) {
            int r = mbase + mt * 16 + gid + h * 8;
            size_t dstrow = 0;
            if (EPI == EPI_PROJ) {
                int w = r / NTOK, n = r - w * NTOK;
                int bi = w >> 6, wi = w & 63, wh = wi >> 3, ww = wi & 7;
                int ii = n / WSZ, jj = n - ii * WSZ;
                int hp = wh * WSZ + ii + SSZ; if (hp >= HIMG) hp -= HIMG;
                int wp = ww * WSZ + jj + SSZ; if (wp >= WIMG) wp -= WIMG;
                dstrow = ((size_t)bi * (HIMG * WIMG) + (size_t)hp * WIMG + wp);
            }
#pragma unroll
            for (int nt = 0; nt < 4; nt++) {
                int n = nbase + nt * 8 + tig * 2;
                float2 bsv = *(const float2*)(bias + n);
                float vx = acc[mt][nt][2 * h]     + bsv.x;
                float vy = acc[mt][nt][2 * h + 1] + bsv.y;
                if (EPI == EPI_PROJ) {
                    size_t dst = dstrow * CDIM + n;
                    float2 xv = *(const float2*)(extra + dst);
                    float2 v; v.x = vx + xv.x; v.y = vy + xv.y;
                    *(float2*)(outf + dst) = v;
                } else { // EPI_FC2
                    float2 xv = *(const float2*)(outf + (size_t)r * CDIM + n);
                    float2 v; v.x = vx + xv.x; v.y = vy + xv.y;
                    *(float2*)(outf + (size_t)r * CDIM + n) = v;
                }
            }
        }
    }
}

// ---------------- tensor-core window attention: 2 heads / block --------------
// 256 threads = two independent 4-warp halves, one head each.
constexpr int AH = 6016;           // u32 per head region
__global__ void __launch_bounds__(256) attn_tc2()
{
    __shared__ uint32_t sm[2 * AH];                 // 48128 B
    constexpr int QS = 0, KS = 1280, VT = 2560, PS = 3712;

    const int blk = blockIdx.x;
    const int w = blk / 3, hp = blk - w * 3;        // head pair index
    const int t = threadIdx.x, lane = t & 31, w8 = t >> 5;
    const int hh = w8 >> 2, w4 = w8 & 3;
    const int gid = lane >> 2, tig = lane & 3;

    char* smc = (char*)sm;
    const __nv_bfloat16* base = g_qkv + (size_t)w * NTOK * QKVC + (size_t)(2 * hp) * HD;

    // Q,K: both heads; (hh2,s) spans 128B contiguous per row
    for (int e = t; e < NTOK * 8; e += 256) {
        int n = e >> 3, q = e & 7, hh2 = q >> 2, s = q & 3;
        const char* rp = (const char*)(base + (size_t)n * QKVC + hh2 * HD) + s * 16;
        int db = hh2 * (AH * 4) + n * 80 + s * 16;
        *(uint4*)(smc + QS * 4 + db) = *(const uint4*)rp;
        *(uint4*)(smc + KS * 4 + db) = *(const uint4*)(rp + CDIM * 2);
    }
    for (int e = t; e < 15 * 8; e += 256) {
        int n = 49 + (e >> 3), q = e & 7, hh2 = q >> 2, s = q & 3;
        int db = hh2 * (AH * 4) + n * 80 + s * 16;
        uint4 z = {0, 0, 0, 0};
        *(uint4*)(smc + QS * 4 + db) = z;
        *(uint4*)(smc + KS * 4 + db) = z;
    }
    // V transposed per head
    for (int e = t; e < NTOK * HD * 2; e += 256) {
        int hh2 = e >= NTOK * HD, e2 = e - hh2 * NTOK * HD;
        int n = e2 >> 5, d = e2 & 31;
        ((__nv_bfloat16*)(smc + hh2 * (AH * 4) + VT * 4 + d * 144))[n] =
            base[(size_t)n * QKVC + 2 * CDIM + hh2 * HD + d];
    }
    for (int e = t; e < HD * 15 * 2; e += 256) {
        int hh2 = e >= HD * 15, e2 = e - hh2 * HD * 15;
        int d = e2 / 15, n = 49 + e2 % 15;
        ((__nv_bfloat16*)(smc + hh2 * (AH * 4) + VT * 4 + d * 144))[n] = __nv_bfloat16(0.f);
    }
    __syncthreads();

    const uint32_t smb = (uint32_t)__cvta_generic_to_shared(sm) + hh * (AH * 4);
    const uint32_t aQ = smb + QS * 4 + (w4 * 16 + (lane & 15)) * 80 + (lane >> 4) * 16;
    const uint32_t bK = smb + KS * 4 +
        ((lane & 7) + ((lane & 16) >> 1)) * 80 + ((lane >> 3) & 1) * 16;
    float acc[8][4];
#pragma unroll
    for (int i = 0; i < 8; i++)
#pragma unroll
        for (int j = 0; j < 4; j++) acc[i][j] = 0.f;
#pragma unroll
    for (int kk = 0; kk < 2; kk++) {
        uint32_t a[4]; ldsm4(a, aQ + kk * 32);
#pragma unroll
        for (int ntp = 0; ntp < 4; ntp++) {
            uint32_t b[4]; ldsm4(b, bK + ntp * 1280u + kk * 32);
            mma_bf(acc[2 * ntp],     a, b[0], b[1]);
            mma_bf(acc[2 * ntp + 1], a, b[2], b[3]);
        }
    }

    const int h = 2 * hp + hh;
    const int wi = w & 63;
    const int cls = (((wi >> 3) == 7) ? 2 : 0) | (((wi & 7) == 7) ? 1 : 0);
    const float* tabh = g_tab + (size_t)(cls * HEADS + h) * NTOK * 64;

    char* smh = smc + hh * (AH * 4);
    const float scale = 0.17677669529663688f;
#pragma unroll
    for (int rr = 0; rr < 2; rr++) {
        int r = w4 * 16 + gid + rr * 8;
        const bool rv = (r < NTOK);
        const float* trow = tabh + (size_t)(rv ? r : 0) * 64 + tig * 2;
        float vv[16]; float mx = -1e30f;
#pragma unroll
        for (int nt = 0; nt < 8; nt++) {
            float2 tv = *(const float2*)(trow + nt * 8);
            float v0 = rv ? acc[nt][2 * rr]     * scale + tv.x : -1e30f;
            float v1 = rv ? acc[nt][2 * rr + 1] * scale + tv.y : -1e30f;
            vv[2 * nt] = v0; vv[2 * nt + 1] = v1;
            mx = fmaxf(mx, fmaxf(v0, v1));
        }
        mx = fmaxf(mx, __shfl_xor_sync(0xffffffffu, mx, 1));
        mx = fmaxf(mx, __shfl_xor_sync(0xffffffffu, mx, 2));
        float sum = 0.f;
#pragma unroll
        for (int i = 0; i < 16; i++) { vv[i] = __expf(vv[i] - mx); sum += vv[i]; }
        sum += __shfl_xor_sync(0xffffffffu, sum, 1);
        sum += __shfl_xor_sync(0xffffffffu, sum, 2);
        float inv = 1.0f / sum;
#pragma unroll
        for (int nt = 0; nt < 8; nt++) {
            int c = nt * 8 + tig * 2;
            __nv_bfloat162 p(__float2bfloat16(vv[2 * nt] * inv),
                             __float2bfloat16(vv[2 * nt + 1] * inv));
            *(__nv_bfloat162*)(smh + PS * 4 + r * 144 + c * 2) = p;
        }
    }
    __syncwarp();

    const uint32_t aP = smb + PS * 4 + (w4 * 16 + (lane & 15)) * 144 + (lane >> 4) * 16;
    const uint32_t bV = smb + VT * 4 +
        ((lane & 7) + ((lane & 16) >> 1)) * 144 + ((lane >> 3) & 1) * 16;
    float oa[4][4];
#pragma unroll
    for (int i = 0; i < 4; i++)
#pragma unroll
        for (int j = 0; j < 4; j++) oa[i][j] = 0.f;
#pragma unroll
    for (int ks = 0; ks < 4; ks++) {
        uint32_t a[4]; ldsm4(a, aP + ks * 32);
        uint32_t b0[4], b1[4];
        ldsm4(b0, bV + ks * 32);
        ldsm4(b1, bV + 16 * 144 + ks * 32);
        mma_bf(oa[0], a, b0[0], b0[1]);
        mma_bf(oa[1], a, b0[2], b0[3]);
        mma_bf(oa[2], a, b1[0], b1[1]);
        mma_bf(oa[3], a, b1[2], b1[3]);
    }
    __nv_bfloat16* ob = g_att + (size_t)w * NTOK * CDIM + (size_t)h * HD;
#pragma unroll
    for (int rr = 0; rr < 2; rr++) {
        int r = w4 * 16 + gid + rr * 8;
        if (r < NTOK) {
#pragma unroll
            for (int nt = 0; nt < 4; nt++) {
                int c = nt * 8 + tig * 2;
                __nv_bfloat162 p(__float2bfloat16(oa[nt][2 * rr]),
                                 __float2bfloat16(oa[nt][2 * rr + 1]));
                *(__nv_bfloat162*)(ob + (size_t)r * CDIM + c) = p;
            }
        }
    }
}

// ---------------- launch ----------------------------------------------------
extern "C" void kernel_launch(void* const* d_in, const int* in_sizes, int n_in,
                              void* d_out, int out_size)
{
    const float* x      = (const float*)d_in[0];
    const float* n1g    = (const float*)d_in[1];
    const float* n1b    = (const float*)d_in[2];
    const float* qkv_w  = (const float*)d_in[3];
    const float* qkv_b  = (const float*)d_in[4];
    const float* relb   = (const float*)d_in[5];
    const float* proj_w = (const float*)d_in[6];
    const float* proj_b = (const float*)d_in[7];
    const float* n2g    = (const float*)d_in[8];
    const float* n2b    = (const float*)d_in[9];
    const float* fc1_w  = (const float*)d_in[10];
    const float* fc1_b  = (const float*)d_in[11];
    const float* fc2_w  = (const float*)d_in[12];
    const float* fc2_b  = (const float*)d_in[13];
    float* out = (float*)d_out;

    __nv_bfloat16 *pxw, *pqkv, *patt, *phid, *pwqkv, *pwproj, *pwfc1, *pwfc2;
    cudaGetSymbolAddress((void**)&pxw,   g_xw);
    cudaGetSymbolAddress((void**)&pqkv,  g_qkv);
    cudaGetSymbolAddress((void**)&patt,  g_att);
    cudaGetSymbolAddress((void**)&phid,  g_hid);
    cudaGetSymbolAddress((void**)&pwqkv, g_wqkv);
    cudaGetSymbolAddress((void**)&pwproj,g_wproj);
    cudaGetSymbolAddress((void**)&pwfc1, g_wfc1);
    cudaGetSymbolAddress((void**)&pwfc2, g_wfc2);

    const int LN_BLOCKS = (int)(ROWS / 8);       // 25088
    const int MB = (int)(ROWS / 128);            // 1568
    constexpr int WTOT = QKVC * CDIM + CDIM * CDIM + HID * CDIM + CDIM * HID;

    w2bf_all<<<(WTOT + 255) / 256, 256>>>(qkv_w, proj_w, fc1_w, fc2_w,
                                          pwqkv, pwproj, pwfc1, pwfc2);
    tab_kernel<<<4 * HEADS, 256>>>(relb);

    ln_kernel<true><<<LN_BLOCKS, 256>>>(x, n1g, n1b);
    gemm_bf96<192, EPI_QKV><<<dim3(QKVC / 96, MB), 128>>>(pxw, pwqkv, qkv_b, pqkv);
    attn_tc2<<<NWIN * 3, 256>>>();
    gemm_bf64<192, EPI_PROJ><<<dim3(CDIM / 64, MB), 128>>>(patt, pwproj, proj_b, out, x);
    ln_kernel<false><<<LN_BLOCKS, 256>>>(out, n2g, n2b);
    gemm_bf96<192, EPI_FC1><<<dim3(HID / 96, MB), 128>>>(pxw, pwfc1, fc1_b, phid);
    gemm_bf64<768, EPI_FC2><<<dim3(CDIM / 64, MB), 128>>>(phid, pwfc2, fc2_b, out, nullptr);
}